// round 1
// baseline (speedup 1.0000x reference)
#include <cuda_runtime.h>
#include <cstdint>

// ---------------- problem constants ----------------
#define B_   64
#define V_   2048
#define K_   128
#define H_   128
#define N_   (B_*V_)        // 131072
#define E_   1048576
#define CF_  47
#define L_   3
#define EPSF 1e-5f
#define SPLITV 8

// ---------------- scratch (device globals; no allocs allowed) ----------------
__device__ float g_Y1[(size_t)E_*H_];        // 512 MB  pre-BN stage1
__device__ float g_Y2[(size_t)E_*2*H_];      // 1 GB    pre-BN stage2
__device__ float g_H [(size_t)N_*H_];        // 64 MB   node features h
__device__ float g_HP[(size_t)N_*H_];        // 64 MB   h_prop
__device__ float g_HS[(size_t)B_*K_*H_];     // 4 MB    spectral coeffs
__device__ float g_Ya[(size_t)N_*H_];        // 64 MB
__device__ float g_Yb[(size_t)N_*H_];        // 64 MB
__device__ float g_sum[256], g_sumsq[256], g_scale[256], g_shift[256];

// ---------------- helpers ----------------
__device__ __forceinline__ float siluf(float x){ return x * (1.f/(1.f+__expf(-x))); }
__device__ __forceinline__ float softplusf(float x){ return x > 20.f ? x : log1pf(__expf(x)); }
__device__ __forceinline__ void red_add_v4(float* a, float x, float y, float z, float w){
    asm volatile("red.global.add.v4.f32 [%0], {%1,%2,%3,%4};"
                 :: "l"(a), "f"(x), "f"(y), "f"(z), "f"(w) : "memory");
}

__global__ void zero_kernel(float* __restrict__ p, size_t n){
    size_t i = (size_t)blockIdx.x*blockDim.x + threadIdx.x;
    if (i < n) p[i] = 0.f;
}
__global__ void zero_stats(){ g_sum[threadIdx.x]=0.f; g_sumsq[threadIdx.x]=0.f; }

// ---------------- generic register-tiled SGEMM ----------------
// C[M,Nd] = op(A)[M,Kd] * B[Kd,Nd] (+bias). 128x128 tile, BK=16, 256 thr, 8x8/thr.
// MODE 0: plain A (row stride lda)
// MODE 1: A' = silu(A*g_scale[k] + g_shift[k])   (fused BN+SiLU)
// MODE 2: A = concat(A0[M,128], A1[M,128]) along k (Kd=256)
template<int MODE>
__global__ void __launch_bounds__(256) gemm_nn(
    const float* __restrict__ A, const float* __restrict__ A1,
    const float* __restrict__ Bm, const float* __restrict__ bias,
    float* __restrict__ C, int M, int Kd, int Nd, int lda,
    size_t sA, size_t sB, size_t sC)
{
    __shared__ float As[16][128];
    __shared__ float Bs[16][128];
    const int tid = threadIdx.x;
    const int bz  = blockIdx.z;
    A  += sA*bz; Bm += sB*bz; C += sC*bz;
    const int brow = blockIdx.y*128;
    const int bcol = blockIdx.x*128;
    const int tx = tid & 15, ty = tid >> 4;
    const int am = tid >> 2;          // 0..63
    const int ak = (tid & 3) * 4;     // 0,4,8,12
    const int bk = tid >> 5;          // 0..7
    const int bn = (tid & 31) * 4;

    float acc[8][8];
    #pragma unroll
    for (int i=0;i<8;i++)
        #pragma unroll
        for (int j=0;j<8;j++) acc[i][j]=0.f;

    for (int kt = 0; kt < Kd; kt += 16) {
        #pragma unroll
        for (int r=0;r<2;r++){
            const int m = brow + am + r*64;
            #pragma unroll
            for (int j=0;j<4;j++){
                const int k = kt + ak + j;
                float v = 0.f;
                if (MODE==2) {
                    v = (k < 128) ? A[(size_t)m*128 + k] : A1[(size_t)m*128 + (k-128)];
                } else {
                    if (k < Kd) {
                        v = A[(size_t)m*lda + k];
                        if (MODE==1) { float xx = v*g_scale[k] + g_shift[k]; v = siluf(xx); }
                    }
                }
                As[ak+j][am + r*64] = v;
            }
        }
        #pragma unroll
        for (int r=0;r<2;r++){
            const int k = kt + bk + r*8;
            float4 v = make_float4(0.f,0.f,0.f,0.f);
            if (k < Kd) v = *reinterpret_cast<const float4*>(Bm + (size_t)k*Nd + bcol + bn);
            *reinterpret_cast<float4*>(&Bs[bk + r*8][bn]) = v;
        }
        __syncthreads();
        #pragma unroll
        for (int k=0;k<16;k++){
            float ra[8], rb[8];
            #pragma unroll
            for (int i=0;i<8;i++) ra[i] = As[k][ty*8+i];
            #pragma unroll
            for (int j=0;j<8;j++) rb[j] = Bs[k][tx*8+j];
            #pragma unroll
            for (int i=0;i<8;i++)
                #pragma unroll
                for (int j=0;j<8;j++)
                    acc[i][j] = fmaf(ra[i], rb[j], acc[i][j]);
        }
        __syncthreads();
    }
    #pragma unroll
    for (int i=0;i<8;i++){
        const int m = brow + ty*8 + i;
        #pragma unroll
        for (int j=0;j<8;j+=4){
            const int n = bcol + tx*8 + j;
            float b0=0.f,b1=0.f,b2=0.f,b3=0.f;
            if (bias){ b0=bias[n]; b1=bias[n+1]; b2=bias[n+2]; b3=bias[n+3]; }
            float4 o;
            o.x = acc[i][j+0]+b0; o.y = acc[i][j+1]+b1;
            o.z = acc[i][j+2]+b2; o.w = acc[i][j+3]+b3;
            *reinterpret_cast<float4*>(C + (size_t)m*Nd + n) = o;
        }
    }
}

// ---------------- spectral forward: HS[b,k,h] += sum_v evecs_inv[b,k,v]*h[b,v,h] ----------------
// A^T*B style; A = eigs[b, 1+V+v, k] (row-major [V,K]), B = h[b] [V,H]. Split over v, atomic out.
__global__ void __launch_bounds__(256) spec_fwd(
    const float* __restrict__ eigs, const float* __restrict__ Hb, float* __restrict__ HS)
{
    const int b   = blockIdx.z;
    const int seg = blockIdx.x;
    const float* A  = eigs + ((size_t)b*(2*V_+1) + 1 + V_) * K_;
    const float* Bm = Hb   + (size_t)b*V_*H_;
    __shared__ float As[16][128];
    __shared__ float Bs[16][128];
    const int tid = threadIdx.x;
    const int tx = tid & 15, ty = tid >> 4;
    const int lr = tid >> 5;
    const int lc = (tid & 31) * 4;

    float acc[8][8];
    #pragma unroll
    for (int i=0;i<8;i++)
        #pragma unroll
        for (int j=0;j<8;j++) acc[i][j]=0.f;

    const int v0 = seg * (V_/SPLITV);
    for (int vt = v0; vt < v0 + V_/SPLITV; vt += 16) {
        #pragma unroll
        for (int r=0;r<2;r++){
            const int v = vt + lr + r*8;
            *reinterpret_cast<float4*>(&As[lr+r*8][lc]) =
                *reinterpret_cast<const float4*>(A  + (size_t)v*K_ + lc);
            *reinterpret_cast<float4*>(&Bs[lr+r*8][lc]) =
                *reinterpret_cast<const float4*>(Bm + (size_t)v*H_ + lc);
        }
        __syncthreads();
        #pragma unroll
        for (int k=0;k<16;k++){
            float ra[8], rb[8];
            #pragma unroll
            for (int i=0;i<8;i++) ra[i] = As[k][ty*8+i];
            #pragma unroll
            for (int j=0;j<8;j++) rb[j] = Bs[k][tx*8+j];
            #pragma unroll
            for (int i=0;i<8;i++)
                #pragma unroll
                for (int j=0;j<8;j++)
                    acc[i][j] = fmaf(ra[i], rb[j], acc[i][j]);
        }
        __syncthreads();
    }
    float* Cb = HS + (size_t)b*K_*H_;
    #pragma unroll
    for (int i=0;i<8;i++)
        #pragma unroll
        for (int j=0;j<8;j+=4)
            red_add_v4(Cb + (size_t)(ty*8+i)*H_ + tx*8 + j,
                       acc[i][j], acc[i][j+1], acc[i][j+2], acc[i][j+3]);
}

// HS[b,k,h] *= exp(-eig[b,k] * max(prop_time[l,h],1e-6))
__global__ void coeff_mul(const float* __restrict__ eigs, const float* __restrict__ pt,
                          float* __restrict__ HS, int l)
{
    const int b = blockIdx.y, k = blockIdx.x, h = threadIdx.x;
    const float ev = eigs[(size_t)b*(2*V_+1)*K_ + k];
    const float t  = fmaxf(pt[l*H_ + h], 1e-6f);
    HS[((size_t)b*K_ + k)*H_ + h] *= __expf(-ev*t);
}

// ---------------- per-column mean/var statistics ----------------
template<int C>
__global__ void colstats(const float* __restrict__ X, long R){
    const int c = threadIdx.x;
    const long per = (R + gridDim.x - 1) / gridDim.x;
    long r0 = (long)blockIdx.x * per;
    long r1 = r0 + per; if (r1 > R) r1 = R;
    float s = 0.f, q = 0.f;
    for (long r = r0; r < r1; r++){
        float v = X[(size_t)r*C + c];
        s += v; q += v*v;
    }
    atomicAdd(&g_sum[c], s);
    atomicAdd(&g_sumsq[c], q);
}

__global__ void finalize_bn(const float* __restrict__ g, const float* __restrict__ be, float Rinv){
    const int c = threadIdx.x;
    const float m   = g_sum[c]*Rinv;
    const float var = g_sumsq[c]*Rinv - m*m;
    const float sc  = g[c] * rsqrtf(var + EPSF);
    g_scale[c] = sc;
    g_shift[c] = be[c] - m*sc;
}

// ---------------- message + scatter-add ----------------
// msg = sigmoid(bn(Y2[:, :128])) * softplus(bn(Y2[:, 128:])); h[vid] += msg
__global__ void msg_scatter(const float* __restrict__ Y2, const int* __restrict__ vid,
                            float* __restrict__ Hout)
{
    const int sub = threadIdx.x >> 5;
    const int c4  = (threadIdx.x & 31) * 4;
    const int e0  = blockIdx.x * 32 + sub * 8;
    const float s0=g_scale[c4],   s1=g_scale[c4+1],   s2=g_scale[c4+2],   s3=g_scale[c4+3];
    const float t0=g_shift[c4],   t1=g_shift[c4+1],   t2=g_shift[c4+2],   t3=g_shift[c4+3];
    const float u0=g_scale[128+c4],u1=g_scale[129+c4],u2=g_scale[130+c4],u3=g_scale[131+c4];
    const float w0=g_shift[128+c4],w1=g_shift[129+c4],w2=g_shift[130+c4],w3=g_shift[131+c4];
    #pragma unroll
    for (int i=0;i<8;i++){
        const int e = e0 + i;
        float4 f = *reinterpret_cast<const float4*>(Y2 + (size_t)e*256 + c4);
        float4 c = *reinterpret_cast<const float4*>(Y2 + (size_t)e*256 + 128 + c4);
        float m0 = (1.f/(1.f+__expf(-(f.x*s0+t0)))) * softplusf(c.x*u0+w0);
        float m1 = (1.f/(1.f+__expf(-(f.y*s1+t1)))) * softplusf(c.y*u1+w1);
        float m2 = (1.f/(1.f+__expf(-(f.z*s2+t2)))) * softplusf(c.z*u2+w2);
        float m3 = (1.f/(1.f+__expf(-(f.w*s3+t3)))) * softplusf(c.w*u3+w3);
        const int v = vid[e];
        red_add_v4(Hout + (size_t)v*128 + c4, m0, m1, m2, m3);
    }
}

// h += bn(Y)
__global__ void h_update(float* __restrict__ H, const float* __restrict__ Y){
    const size_t i = (size_t)blockIdx.x*256 + threadIdx.x;
    const int c = (int)(i & 127);
    H[i] += Y[i]*g_scale[c] + g_shift[c];
}

// out[b] += mean_v( silu(bn(Yo)) . wo2 + bo2 )
__global__ void out_reduce(const float* __restrict__ Yo, const float* __restrict__ wo2,
                           const float* __restrict__ bo2, float* __restrict__ out)
{
    const int warp = threadIdx.x >> 5, lane = threadIdx.x & 31;
    const long n = (long)blockIdx.x*8 + warp;
    float s = 0.f;
    #pragma unroll
    for (int j=0;j<4;j++){
        const int h = lane + j*32;
        float x = Yo[(size_t)n*128 + h]*g_scale[h] + g_shift[h];
        x = siluf(x);
        s += x * wo2[h];
    }
    #pragma unroll
    for (int o=16;o>0;o>>=1) s += __shfl_xor_sync(0xFFFFFFFFu, s, o);
    if (lane == 0){
        const int b = (int)(n >> 11);   // n / 2048
        atomicAdd(&out[b], (s + bo2[0]) * (1.f/(float)V_));
    }
}

// ---------------- launcher ----------------
extern "C" void kernel_launch(void* const* d_in, const int* in_sizes, int n_in,
                              void* d_out, int out_size)
{
    const float* chem = (const float*)d_in[0];
    const int*   vid  = (const int*  )d_in[1];
    const float* eigs = (const float*)d_in[2];
    const float* w1   = (const float*)d_in[3];
    const float* b1   = (const float*)d_in[4];
    const float* g1   = (const float*)d_in[5];
    const float* be1  = (const float*)d_in[6];
    const float* w2   = (const float*)d_in[7];
    const float* b2   = (const float*)d_in[8];
    const float* g2   = (const float*)d_in[9];
    const float* be2  = (const float*)d_in[10];
    const float* ptim = (const float*)d_in[11];
    const float* pw1  = (const float*)d_in[12];
    const float* pb1  = (const float*)d_in[13];
    const float* pg1  = (const float*)d_in[14];
    const float* pbe1 = (const float*)d_in[15];
    const float* pw2  = (const float*)d_in[16];
    const float* pb2  = (const float*)d_in[17];
    const float* pg2  = (const float*)d_in[18];
    const float* pbe2 = (const float*)d_in[19];
    const float* wo1  = (const float*)d_in[20];
    const float* bo1  = (const float*)d_in[21];
    const float* go1  = (const float*)d_in[22];
    const float* beo1 = (const float*)d_in[23];
    const float* wo2  = (const float*)d_in[24];
    const float* bo2  = (const float*)d_in[25];
    float* outp = (float*)d_out;

    void* p;
    float *pY1,*pY2,*pH,*pHP,*pHS,*pYa,*pYb;
    cudaGetSymbolAddress(&p, g_Y1); pY1=(float*)p;
    cudaGetSymbolAddress(&p, g_Y2); pY2=(float*)p;
    cudaGetSymbolAddress(&p, g_H ); pH =(float*)p;
    cudaGetSymbolAddress(&p, g_HP); pHP=(float*)p;
    cudaGetSymbolAddress(&p, g_HS); pHS=(float*)p;
    cudaGetSymbolAddress(&p, g_Ya); pYa=(float*)p;
    cudaGetSymbolAddress(&p, g_Yb); pYb=(float*)p;

    // output init (poisoned by harness)
    zero_kernel<<<1, 64>>>(outp, 64);

    // ---- chem MLP stage 1: Y1 = chem @ w1 + b1 ----
    gemm_nn<0><<<dim3(1, E_/128, 1), 256>>>(chem, nullptr, w1, b1, pY1,
                                            E_, CF_, 128, CF_, 0, 0, 0);
    zero_stats<<<1,256>>>();
    colstats<128><<<2048,128>>>(pY1, (long)E_);
    finalize_bn<<<1,128>>>(g1, be1, 1.f/(float)E_);

    // ---- stage 2: Y2 = silu(bn(Y1)) @ w2 + b2 ----
    gemm_nn<1><<<dim3(2, E_/128, 1), 256>>>(pY1, nullptr, w2, b2, pY2,
                                            E_, 128, 256, 128, 0, 0, 0);
    zero_stats<<<1,256>>>();
    colstats<256><<<2048,256>>>(pY2, (long)E_);
    finalize_bn<<<1,256>>>(g2, be2, 1.f/(float)E_);

    // ---- message + segment_sum ----
    zero_kernel<<<(unsigned)(((size_t)N_*H_)/256), 256>>>(pH, (size_t)N_*H_);
    msg_scatter<<<E_/32, 128>>>(pY2, vid, pH);

    // ---- propagation layers ----
    for (int l = 0; l < L_; l++){
        zero_kernel<<<(B_*K_*H_+255)/256, 256>>>(pHS, (size_t)B_*K_*H_);
        spec_fwd<<<dim3(SPLITV,1,B_), 256>>>(eigs, pH, pHS);
        coeff_mul<<<dim3(K_,B_), H_>>>(eigs, ptim, pHS, l);
        // h_prop = evecs @ (coeff * h_spec), batched over B
        gemm_nn<0><<<dim3(1, V_/128, B_), 256>>>(eigs + K_, nullptr, pHS, nullptr, pHP,
                                                 V_, K_, H_, K_,
                                                 (size_t)(2*V_+1)*K_, (size_t)K_*H_, (size_t)V_*H_);
        // z-MLP stage 1: Ya = [h, h_prop] @ pw1[l] + pb1[l]
        gemm_nn<2><<<dim3(1, N_/128, 1), 256>>>(pH, pHP, pw1 + (size_t)l*2*H_*H_, pb1 + l*H_,
                                                pYa, N_, 256, 128, 128, 0, 0, 0);
        zero_stats<<<1,256>>>();
        colstats<128><<<512,128>>>(pYa, (long)N_);
        finalize_bn<<<1,128>>>(pg1 + l*H_, pbe1 + l*H_, 1.f/(float)N_);
        // z-MLP stage 2: Yb = silu(bn(Ya)) @ pw2[l] + pb2[l]
        gemm_nn<1><<<dim3(1, N_/128, 1), 256>>>(pYa, nullptr, pw2 + (size_t)l*H_*H_, pb2 + l*H_,
                                                pYb, N_, 128, 128, 128, 0, 0, 0);
        zero_stats<<<1,256>>>();
        colstats<128><<<512,128>>>(pYb, (long)N_);
        finalize_bn<<<1,128>>>(pg2 + l*H_, pbe2 + l*H_, 1.f/(float)N_);
        // h += bn(Yb)
        h_update<<<(unsigned)(((size_t)N_*H_)/256), 256>>>(pH, pYb);
    }

    // ---- output head ----
    gemm_nn<0><<<dim3(1, N_/128, 1), 256>>>(pH, nullptr, wo1, bo1, pYa,
                                            N_, 128, 128, 128, 0, 0, 0);
    zero_stats<<<1,256>>>();
    colstats<128><<<512,128>>>(pYa, (long)N_);
    finalize_bn<<<1,128>>>(go1, beo1, 1.f/(float)N_);
    out_reduce<<<N_/8, 256>>>(pYa, wo2, bo2, outp);
}

// round 2
// speedup vs baseline: 1.0704x; 1.0704x over previous
#include <cuda_runtime.h>
#include <cstdint>

// ---------------- problem constants ----------------
#define B_   64
#define V_   2048
#define K_   128
#define H_   128
#define N_   (B_*V_)        // 131072
#define E_   1048576
#define CF_  47
#define L_   3
#define EPSF 1e-5f
#define SPLITV 8

// ---------------- scratch (device globals; no allocs allowed) ----------------
__device__ float g_Y1[(size_t)E_*H_];        // 512 MB  pre-BN stage1
__device__ float g_Y2[(size_t)E_*2*H_];      // 1 GB    pre-BN stage2
__device__ float g_H [(size_t)N_*H_];        // 64 MB   node features h
__device__ float g_HP[(size_t)N_*H_];        // 64 MB   h_prop
__device__ float g_HS[(size_t)B_*K_*H_];     // 4 MB    spectral coeffs
__device__ float g_Ya[(size_t)N_*H_];        // 64 MB
__device__ float g_Yb[(size_t)N_*H_];        // 64 MB
__device__ float g_sum[256], g_sumsq[256], g_scale[256], g_shift[256];

// ---------------- helpers ----------------
__device__ __forceinline__ float siluf(float x){ return x * (1.f/(1.f+__expf(-x))); }
__device__ __forceinline__ float softplusf(float x){ return x > 20.f ? x : log1pf(__expf(x)); }
__device__ __forceinline__ void red_add_v4(float* a, float x, float y, float z, float w){
    asm volatile("red.global.add.v4.f32 [%0], {%1,%2,%3,%4};"
                 :: "l"(a), "f"(x), "f"(y), "f"(z), "f"(w) : "memory");
}
// packed fp32 FMA (FFMA2): d = a*b + d, lanewise on (lo,hi)
__device__ __forceinline__ void ffma2(unsigned long long &d, unsigned long long a, unsigned long long b){
    asm("fma.rn.f32x2 %0, %1, %2, %0;" : "+l"(d) : "l"(a), "l"(b));
}
__device__ __forceinline__ unsigned long long dup2(float v){
    unsigned u = __float_as_uint(v);
    return ((unsigned long long)u << 32) | (unsigned long long)u;
}
__device__ __forceinline__ float2 ull_as_f2(unsigned long long v){
    float2 f;
    f.x = __uint_as_float((unsigned)(v & 0xffffffffull));
    f.y = __uint_as_float((unsigned)(v >> 32));
    return f;
}

__global__ void zero_kernel(float* __restrict__ p, size_t n){
    size_t i = (size_t)blockIdx.x*blockDim.x + threadIdx.x;
    if (i < n) p[i] = 0.f;
}
__global__ void zero_stats(){ g_sum[threadIdx.x]=0.f; g_sumsq[threadIdx.x]=0.f; }

// ---------------- FFMA2 register-tiled SGEMM ----------------
// C[M,Nd] = op(A)[M,Kd] * B[Kd,Nd] (+bias). 128x128 tile, BK=16, 256 thr, 8x8/thr.
// MODE 0: plain A (row stride lda)
// MODE 1: A' = silu(A*g_scale[k] + g_shift[k])   (fused BN+SiLU), Kd=128
// MODE 2: A = concat(A0[M,128], A1[M,128]) along k (Kd=256)
// STATS : accumulate per-column sum / sumsq of C into g_sum / g_sumsq
template<int MODE, bool STATS>
__global__ void __launch_bounds__(256) gemm2x(
    const float* __restrict__ A, const float* __restrict__ A1,
    const float* __restrict__ Bm, const float* __restrict__ bias,
    float* __restrict__ C, int M, int Kd, int Nd, int lda,
    size_t sA, size_t sB, size_t sC)
{
    __shared__ unsigned long long As2[16*128];   // duplicated pairs: As2[k*128+m] = (a,a)
    __shared__ float Bs[16][128];
    const int tid = threadIdx.x;
    const int bz  = blockIdx.z;
    A  += sA*bz; Bm += sB*bz; C += sC*bz;
    const int brow = blockIdx.y*128;
    const int bcol = blockIdx.x*128;
    const int tx = tid & 15, ty = tid >> 4;
    const int am  = tid >> 1;          // 0..127 (A row within tile)
    const int ak0 = (tid & 1) * 8;     // 0 or 8 (k sub-chunk)
    const int bk  = tid >> 5;          // 0..7
    const int bn  = (tid & 31) * 4;

    const bool avec = (MODE == 2) || (((lda & 3) == 0) && ((Kd & 15) == 0));

    unsigned long long acc2[8][4];
    #pragma unroll
    for (int i=0;i<8;i++)
        #pragma unroll
        for (int j=0;j<4;j++) acc2[i][j] = 0ull;

    for (int kt = 0; kt < Kd; kt += 16) {
        // ---- load & transform A chunk (8 contiguous k's for one row) ----
        float av[8];
        if (MODE == 2) {
            const int k0 = kt + ak0;
            const float* S = (k0 < 128) ? (A  + (size_t)(brow+am)*128 + k0)
                                        : (A1 + (size_t)(brow+am)*128 + (k0-128));
            float4 x = *reinterpret_cast<const float4*>(S);
            float4 y = *reinterpret_cast<const float4*>(S+4);
            av[0]=x.x; av[1]=x.y; av[2]=x.z; av[3]=x.w;
            av[4]=y.x; av[5]=y.y; av[6]=y.z; av[7]=y.w;
        } else if (avec) {
            const float* S = A + (size_t)(brow+am)*lda + kt + ak0;
            float4 x = *reinterpret_cast<const float4*>(S);
            float4 y = *reinterpret_cast<const float4*>(S+4);
            av[0]=x.x; av[1]=x.y; av[2]=x.z; av[3]=x.w;
            av[4]=y.x; av[5]=y.y; av[6]=y.z; av[7]=y.w;
        } else {
            #pragma unroll
            for (int q=0;q<8;q++){
                const int k = kt + ak0 + q;
                av[q] = (k < Kd) ? A[(size_t)(brow+am)*lda + k] : 0.f;
            }
        }
        if (MODE == 1) {
            #pragma unroll
            for (int q=0;q<8;q++){
                const int k = kt + ak0 + q;
                float xx = av[q]*g_scale[k] + g_shift[k];
                av[q] = siluf(xx);
            }
        }
        #pragma unroll
        for (int q=0;q<8;q++)
            As2[(ak0+q)*128 + am] = dup2(av[q]);

        // ---- load B chunk ----
        #pragma unroll
        for (int r=0;r<2;r++){
            const int k = kt + bk + r*8;
            float4 v = make_float4(0.f,0.f,0.f,0.f);
            if (k < Kd) v = *reinterpret_cast<const float4*>(Bm + (size_t)k*Nd + bcol + bn);
            *reinterpret_cast<float4*>(&Bs[bk + r*8][bn]) = v;
        }
        __syncthreads();

        // ---- FFMA2 inner loop ----
        #pragma unroll
        for (int k=0;k<16;k++){
            const ulonglong2* ap = reinterpret_cast<const ulonglong2*>(&As2[k*128 + ty*8]);
            ulonglong2 a01 = ap[0], a23 = ap[1], a45 = ap[2], a67 = ap[3];
            const ulonglong2* bp = reinterpret_cast<const ulonglong2*>(&Bs[k][tx*8]);
            ulonglong2 b01 = bp[0], b23 = bp[1];
            unsigned long long ra[8] = {a01.x,a01.y,a23.x,a23.y,a45.x,a45.y,a67.x,a67.y};
            unsigned long long rb[4] = {b01.x,b01.y,b23.x,b23.y};
            #pragma unroll
            for (int i=0;i<8;i++)
                #pragma unroll
                for (int j=0;j<4;j++)
                    ffma2(acc2[i][j], ra[i], rb[j]);
        }
        __syncthreads();
    }

    // ---- epilogue: unpack, add bias, store ----
    float cf[8][8];
    #pragma unroll
    for (int i=0;i<8;i++)
        #pragma unroll
        for (int j=0;j<4;j++){
            float2 p = ull_as_f2(acc2[i][j]);
            cf[i][2*j]   = p.x;
            cf[i][2*j+1] = p.y;
        }
    #pragma unroll
    for (int i=0;i<8;i++){
        const int m = brow + ty*8 + i;
        #pragma unroll
        for (int j=0;j<8;j+=4){
            const int n = bcol + tx*8 + j;
            float b0=0.f,b1=0.f,b2=0.f,b3=0.f;
            if (bias){ b0=bias[n]; b1=bias[n+1]; b2=bias[n+2]; b3=bias[n+3]; }
            float4 o;
            o.x = cf[i][j+0]+b0; o.y = cf[i][j+1]+b1;
            o.z = cf[i][j+2]+b2; o.w = cf[i][j+3]+b3;
            cf[i][j+0]=o.x; cf[i][j+1]=o.y; cf[i][j+2]=o.z; cf[i][j+3]=o.w;
            *reinterpret_cast<float4*>(C + (size_t)m*Nd + n) = o;
        }
    }

    // ---- fused per-column stats ----
    if (STATS){
        float* red = reinterpret_cast<float*>(As2);   // 4096 floats available
        float s[8], q[8];
        #pragma unroll
        for (int j=0;j<8;j++){ s[j]=0.f; q[j]=0.f; }
        #pragma unroll
        for (int i=0;i<8;i++)
            #pragma unroll
            for (int j=0;j<8;j++){ s[j]+=cf[i][j]; q[j]+=cf[i][j]*cf[i][j]; }
        #pragma unroll
        for (int j=0;j<8;j++){
            red[ty*128 + tx*8+j]        = s[j];
            red[2048 + ty*128 + tx*8+j] = q[j];
        }
        __syncthreads();
        if (tid < 128){
            float S=0.f, Q=0.f;
            #pragma unroll
            for (int t=0;t<16;t++){ S += red[t*128+tid]; Q += red[2048+t*128+tid]; }
            atomicAdd(&g_sum[bcol+tid], S);
            atomicAdd(&g_sumsq[bcol+tid], Q);
        }
    }
}

// ---------------- spectral forward (FFMA2): HS[b,k,h] += sum_v evecs_inv[b,k,v]*h[b,v,h] ----------------
__global__ void __launch_bounds__(256) spec_fwd2(
    const float* __restrict__ eigs, const float* __restrict__ Hb, float* __restrict__ HS)
{
    const int b   = blockIdx.z;
    const int seg = blockIdx.x;
    const float* A  = eigs + ((size_t)b*(2*V_+1) + 1 + V_) * K_;   // [V,K] row-major
    const float* Bm = Hb   + (size_t)b*V_*H_;                      // [V,H]
    __shared__ unsigned long long As2[16*128];
    __shared__ float Bs[16][128];
    const int tid = threadIdx.x;
    const int tx = tid & 15, ty = tid >> 4;
    const int lr = ty;            // v row 0..15
    const int lc = tx * 8;        // 8 contiguous cols

    unsigned long long acc2[8][4];
    #pragma unroll
    for (int i=0;i<8;i++)
        #pragma unroll
        for (int j=0;j<4;j++) acc2[i][j]=0ull;

    const int v0 = seg * (V_/SPLITV);
    for (int vt = v0; vt < v0 + V_/SPLITV; vt += 16) {
        const int v = vt + lr;
        float4 a0 = *reinterpret_cast<const float4*>(A  + (size_t)v*K_ + lc);
        float4 a1 = *reinterpret_cast<const float4*>(A  + (size_t)v*K_ + lc + 4);
        As2[lr*128 + lc+0] = dup2(a0.x); As2[lr*128 + lc+1] = dup2(a0.y);
        As2[lr*128 + lc+2] = dup2(a0.z); As2[lr*128 + lc+3] = dup2(a0.w);
        As2[lr*128 + lc+4] = dup2(a1.x); As2[lr*128 + lc+5] = dup2(a1.y);
        As2[lr*128 + lc+6] = dup2(a1.z); As2[lr*128 + lc+7] = dup2(a1.w);
        *reinterpret_cast<float4*>(&Bs[lr][lc])   = *reinterpret_cast<const float4*>(Bm + (size_t)v*H_ + lc);
        *reinterpret_cast<float4*>(&Bs[lr][lc+4]) = *reinterpret_cast<const float4*>(Bm + (size_t)v*H_ + lc + 4);
        __syncthreads();
        #pragma unroll
        for (int k=0;k<16;k++){
            const ulonglong2* ap = reinterpret_cast<const ulonglong2*>(&As2[k*128 + ty*8]);
            ulonglong2 a01 = ap[0], a23 = ap[1], a45 = ap[2], a67 = ap[3];
            const ulonglong2* bp = reinterpret_cast<const ulonglong2*>(&Bs[k][tx*8]);
            ulonglong2 b01 = bp[0], b23 = bp[1];
            unsigned long long ra[8] = {a01.x,a01.y,a23.x,a23.y,a45.x,a45.y,a67.x,a67.y};
            unsigned long long rb[4] = {b01.x,b01.y,b23.x,b23.y};
            #pragma unroll
            for (int i=0;i<8;i++)
                #pragma unroll
                for (int j=0;j<4;j++)
                    ffma2(acc2[i][j], ra[i], rb[j]);
        }
        __syncthreads();
    }
    float* Cb = HS + (size_t)b*K_*H_;
    #pragma unroll
    for (int i=0;i<8;i++){
        float2 p0 = ull_as_f2(acc2[i][0]);
        float2 p1 = ull_as_f2(acc2[i][1]);
        float2 p2 = ull_as_f2(acc2[i][2]);
        float2 p3 = ull_as_f2(acc2[i][3]);
        red_add_v4(Cb + (size_t)(ty*8+i)*H_ + tx*8 + 0, p0.x, p0.y, p1.x, p1.y);
        red_add_v4(Cb + (size_t)(ty*8+i)*H_ + tx*8 + 4, p2.x, p2.y, p3.x, p3.y);
    }
}

// HS[b,k,h] *= exp(-eig[b,k] * max(prop_time[l,h],1e-6))
__global__ void coeff_mul(const float* __restrict__ eigs, const float* __restrict__ pt,
                          float* __restrict__ HS, int l)
{
    const int b = blockIdx.y, k = blockIdx.x, h = threadIdx.x;
    const float ev = eigs[(size_t)b*(2*V_+1)*K_ + k];
    const float t  = fmaxf(pt[l*H_ + h], 1e-6f);
    HS[((size_t)b*K_ + k)*H_ + h] *= __expf(-ev*t);
}

__global__ void finalize_bn(const float* __restrict__ g, const float* __restrict__ be, float Rinv){
    const int c = threadIdx.x;
    const float m   = g_sum[c]*Rinv;
    const float var = g_sumsq[c]*Rinv - m*m;
    const float sc  = g[c] * rsqrtf(var + EPSF);
    g_scale[c] = sc;
    g_shift[c] = be[c] - m*sc;
}

// ---------------- message + scatter-add ----------------
__global__ void msg_scatter(const float* __restrict__ Y2, const int* __restrict__ vid,
                            float* __restrict__ Hout)
{
    const int sub = threadIdx.x >> 5;
    const int c4  = (threadIdx.x & 31) * 4;
    const int e0  = blockIdx.x * 32 + sub * 8;
    const float s0=g_scale[c4],   s1=g_scale[c4+1],   s2=g_scale[c4+2],   s3=g_scale[c4+3];
    const float t0=g_shift[c4],   t1=g_shift[c4+1],   t2=g_shift[c4+2],   t3=g_shift[c4+3];
    const float u0=g_scale[128+c4],u1=g_scale[129+c4],u2=g_scale[130+c4],u3=g_scale[131+c4];
    const float w0=g_shift[128+c4],w1=g_shift[129+c4],w2=g_shift[130+c4],w3=g_shift[131+c4];
    #pragma unroll
    for (int i=0;i<8;i++){
        const int e = e0 + i;
        float4 f = *reinterpret_cast<const float4*>(Y2 + (size_t)e*256 + c4);
        float4 c = *reinterpret_cast<const float4*>(Y2 + (size_t)e*256 + 128 + c4);
        float m0 = (1.f/(1.f+__expf(-(f.x*s0+t0)))) * softplusf(c.x*u0+w0);
        float m1 = (1.f/(1.f+__expf(-(f.y*s1+t1)))) * softplusf(c.y*u1+w1);
        float m2 = (1.f/(1.f+__expf(-(f.z*s2+t2)))) * softplusf(c.z*u2+w2);
        float m3 = (1.f/(1.f+__expf(-(f.w*s3+t3)))) * softplusf(c.w*u3+w3);
        const int v = vid[e];
        red_add_v4(Hout + (size_t)v*128 + c4, m0, m1, m2, m3);
    }
}

// h += bn(Y)
__global__ void h_update(float* __restrict__ H, const float* __restrict__ Y){
    const size_t i = (size_t)blockIdx.x*256 + threadIdx.x;
    const int c = (int)(i & 127);
    H[i] += Y[i]*g_scale[c] + g_shift[c];
}

// out[b] += mean_v( silu(bn(Yo)) . wo2 + bo2 )
__global__ void out_reduce(const float* __restrict__ Yo, const float* __restrict__ wo2,
                           const float* __restrict__ bo2, float* __restrict__ out)
{
    const int warp = threadIdx.x >> 5, lane = threadIdx.x & 31;
    const long n = (long)blockIdx.x*8 + warp;
    float s = 0.f;
    #pragma unroll
    for (int j=0;j<4;j++){
        const int h = lane + j*32;
        float x = Yo[(size_t)n*128 + h]*g_scale[h] + g_shift[h];
        x = siluf(x);
        s += x * wo2[h];
    }
    #pragma unroll
    for (int o=16;o>0;o>>=1) s += __shfl_xor_sync(0xFFFFFFFFu, s, o);
    if (lane == 0){
        const int b = (int)(n >> 11);
        atomicAdd(&out[b], (s + bo2[0]) * (1.f/(float)V_));
    }
}

// ---------------- launcher ----------------
extern "C" void kernel_launch(void* const* d_in, const int* in_sizes, int n_in,
                              void* d_out, int out_size)
{
    const float* chem = (const float*)d_in[0];
    const int*   vid  = (const int*  )d_in[1];
    const float* eigs = (const float*)d_in[2];
    const float* w1   = (const float*)d_in[3];
    const float* b1   = (const float*)d_in[4];
    const float* g1   = (const float*)d_in[5];
    const float* be1  = (const float*)d_in[6];
    const float* w2   = (const float*)d_in[7];
    const float* b2   = (const float*)d_in[8];
    const float* g2   = (const float*)d_in[9];
    const float* be2  = (const float*)d_in[10];
    const float* ptim = (const float*)d_in[11];
    const float* pw1  = (const float*)d_in[12];
    const float* pb1  = (const float*)d_in[13];
    const float* pg1  = (const float*)d_in[14];
    const float* pbe1 = (const float*)d_in[15];
    const float* pw2  = (const float*)d_in[16];
    const float* pb2  = (const float*)d_in[17];
    const float* pg2  = (const float*)d_in[18];
    const float* pbe2 = (const float*)d_in[19];
    const float* wo1  = (const float*)d_in[20];
    const float* bo1  = (const float*)d_in[21];
    const float* go1  = (const float*)d_in[22];
    const float* beo1 = (const float*)d_in[23];
    const float* wo2  = (const float*)d_in[24];
    const float* bo2  = (const float*)d_in[25];
    float* outp = (float*)d_out;

    void* p;
    float *pY1,*pY2,*pH,*pHP,*pHS,*pYa,*pYb;
    cudaGetSymbolAddress(&p, g_Y1); pY1=(float*)p;
    cudaGetSymbolAddress(&p, g_Y2); pY2=(float*)p;
    cudaGetSymbolAddress(&p, g_H ); pH =(float*)p;
    cudaGetSymbolAddress(&p, g_HP); pHP=(float*)p;
    cudaGetSymbolAddress(&p, g_HS); pHS=(float*)p;
    cudaGetSymbolAddress(&p, g_Ya); pYa=(float*)p;
    cudaGetSymbolAddress(&p, g_Yb); pYb=(float*)p;

    zero_kernel<<<1, 64>>>(outp, 64);

    // ---- chem MLP stage 1: Y1 = chem @ w1 + b1 (stats fused) ----
    zero_stats<<<1,256>>>();
    gemm2x<0,true><<<dim3(1, E_/128, 1), 256>>>(chem, nullptr, w1, b1, pY1,
                                                E_, CF_, 128, CF_, 0, 0, 0);
    finalize_bn<<<1,128>>>(g1, be1, 1.f/(float)E_);

    // ---- stage 2: Y2 = silu(bn(Y1)) @ w2 + b2 (stats fused) ----
    zero_stats<<<1,256>>>();
    gemm2x<1,true><<<dim3(2, E_/128, 1), 256>>>(pY1, nullptr, w2, b2, pY2,
                                                E_, 128, 256, 128, 0, 0, 0);
    finalize_bn<<<1,256>>>(g2, be2, 1.f/(float)E_);

    // ---- message + segment_sum ----
    zero_kernel<<<(unsigned)(((size_t)N_*H_)/256), 256>>>(pH, (size_t)N_*H_);
    msg_scatter<<<E_/32, 128>>>(pY2, vid, pH);

    // ---- propagation layers ----
    for (int l = 0; l < L_; l++){
        zero_kernel<<<(B_*K_*H_+255)/256, 256>>>(pHS, (size_t)B_*K_*H_);
        spec_fwd2<<<dim3(SPLITV,1,B_), 256>>>(eigs, pH, pHS);
        coeff_mul<<<dim3(K_,B_), H_>>>(eigs, ptim, pHS, l);
        // h_prop = evecs @ (coeff * h_spec), batched over B
        gemm2x<0,false><<<dim3(1, V_/128, B_), 256>>>(eigs + K_, nullptr, pHS, nullptr, pHP,
                                                      V_, K_, H_, K_,
                                                      (size_t)(2*V_+1)*K_, (size_t)K_*H_, (size_t)V_*H_);
        // z-MLP stage 1: Ya = [h, h_prop] @ pw1[l] + pb1[l] (stats fused)
        zero_stats<<<1,256>>>();
        gemm2x<2,true><<<dim3(1, N_/128, 1), 256>>>(pH, pHP, pw1 + (size_t)l*2*H_*H_, pb1 + l*H_,
                                                    pYa, N_, 256, 128, 128, 0, 0, 0);
        finalize_bn<<<1,128>>>(pg1 + l*H_, pbe1 + l*H_, 1.f/(float)N_);
        // z-MLP stage 2: Yb = silu(bn(Ya)) @ pw2[l] + pb2[l] (stats fused)
        zero_stats<<<1,256>>>();
        gemm2x<1,true><<<dim3(1, N_/128, 1), 256>>>(pYa, nullptr, pw2 + (size_t)l*H_*H_, pb2 + l*H_,
                                                    pYb, N_, 128, 128, 128, 0, 0, 0);
        finalize_bn<<<1,128>>>(pg2 + l*H_, pbe2 + l*H_, 1.f/(float)N_);
        h_update<<<(unsigned)(((size_t)N_*H_)/256), 256>>>(pH, pYb);
    }

    // ---- output head ----
    zero_stats<<<1,256>>>();
    gemm2x<0,true><<<dim3(1, N_/128, 1), 256>>>(pH, nullptr, wo1, bo1, pYa,
                                                N_, 128, 128, 128, 0, 0, 0);
    finalize_bn<<<1,128>>>(go1, beo1, 1.f/(float)N_);
    out_reduce<<<N_/8, 256>>>(pYa, wo2, bo2, outp);
}

// round 4
// speedup vs baseline: 1.7888x; 1.6711x over previous
#include <cuda_runtime.h>
#include <cuda_bf16.h>
#include <cstdint>

// ---------------- problem constants ----------------
#define B_   64
#define V_   2048
#define K_   128
#define H_   128
#define N_   (B_*V_)        // 131072
#define E_   1048576
#define CF_  47
#define L_   3
#define EPSF 1e-5f
#define SPLITV 4

// ---------------- scratch ----------------
__device__ float g_Y1[(size_t)E_*H_];
__device__ float g_Y2[(size_t)E_*2*H_];
__device__ float g_H [(size_t)N_*H_];
__device__ float g_HP[(size_t)N_*H_];
__device__ float g_HS[(size_t)B_*K_*H_];
__device__ float g_Ya[(size_t)N_*H_];
__device__ float g_Yb[(size_t)N_*H_];
__device__ float g_sum[256], g_sumsq[256], g_scale[256], g_shift[256];

// ---------------- scalar helpers ----------------
__device__ __forceinline__ float siluf(float x){ return x * (1.f/(1.f+__expf(-x))); }
__device__ __forceinline__ float softplusf(float x){ return x > 20.f ? x : log1pf(__expf(x)); }
__device__ __forceinline__ void red_add_v4(float* a, float x, float y, float z, float w){
    asm volatile("red.global.add.v4.f32 [%0], {%1,%2,%3,%4};"
                 :: "l"(a), "f"(x), "f"(y), "f"(z), "f"(w) : "memory");
}
__device__ __forceinline__ void red_add_v2(float* a, float x, float y){
    asm volatile("red.global.add.v2.f32 [%0], {%1,%2};"
                 :: "l"(a), "f"(x), "f"(y) : "memory");
}
__device__ __forceinline__ uint32_t smem_u32(const void* p){
    uint32_t a;
    asm("{ .reg .u64 t; cvta.to.shared.u64 t, %1; cvt.u32.u64 %0, t; }" : "=r"(a) : "l"(p));
    return a;
}

// ---------------- HMMA primitives (baseline PTX, no 'a'-arch features) ----------------
__device__ __forceinline__ void ldsm4(uint32_t* r, uint32_t addr){
    asm volatile("ldmatrix.sync.aligned.m8n8.x4.shared.b16 {%0,%1,%2,%3}, [%4];"
        : "=r"(r[0]),"=r"(r[1]),"=r"(r[2]),"=r"(r[3]) : "r"(addr));
}
__device__ __forceinline__ void ldsm4t(uint32_t* r, uint32_t addr){
    asm volatile("ldmatrix.sync.aligned.m8n8.x4.trans.shared.b16 {%0,%1,%2,%3}, [%4];"
        : "=r"(r[0]),"=r"(r[1]),"=r"(r[2]),"=r"(r[3]) : "r"(addr));
}
__device__ __forceinline__ void mma16816(float* d, const uint32_t* a, uint32_t b0, uint32_t b1){
    asm volatile("mma.sync.aligned.m16n8k16.row.col.f32.bf16.bf16.f32 "
        "{%0,%1,%2,%3}, {%4,%5,%6,%7}, {%8,%9}, {%0,%1,%2,%3};"
        : "+f"(d[0]),"+f"(d[1]),"+f"(d[2]),"+f"(d[3])
        : "r"(a[0]),"r"(a[1]),"r"(a[2]),"r"(a[3]), "r"(b0),"r"(b1));
}

// split fp32 -> bf16 hi/lo, 8 elements -> two uint4 (packed bf16x2)
__device__ __forceinline__ void split8(const float* f, uint4& hi, uint4& lo){
    unsigned h[4], l[4];
    #pragma unroll
    for (int p=0;p<4;p++){
        float2 a = make_float2(f[2*p], f[2*p+1]);
        __nv_bfloat162 bh = __float22bfloat162_rn(a);
        float hx = __bfloat162float(bh.x), hy = __bfloat162float(bh.y);
        float2 rz = make_float2(a.x - hx, a.y - hy);
        __nv_bfloat162 bl = __float22bfloat162_rn(rz);
        h[p] = *reinterpret_cast<unsigned*>(&bh);
        l[p] = *reinterpret_cast<unsigned*>(&bl);
    }
    hi = make_uint4(h[0],h[1],h[2],h[3]);
    lo = make_uint4(l[0],l[1],l[2],l[3]);
}

__global__ void zero_kernel(float* __restrict__ p, size_t n){
    size_t i = (size_t)blockIdx.x*blockDim.x + threadIdx.x;
    if (i < n) p[i] = 0.f;
}
__global__ void zero_stats(){ g_sum[threadIdx.x]=0.f; g_sumsq[threadIdx.x]=0.f; }

// ================= HMMA split-bf16 GEMM =================
// C[M,Nd] = op(A)[M,Kd] @ B[Kd,Nd] (+bias), fp32 accum (3-term split-bf16).
// MODE 0: plain A (row stride lda; scalar guarded path when lda%4!=0 or Kd%32!=0)
// MODE 1: A' = silu(A*g_scale[k]+g_shift[k]), Kd=128, lda%4==0
// MODE 2: A = concat(A0[M,128], A1[M,128]) along k (Kd=256)
// Tile 128x128, 8 warps (4m x 2n), warp 32x64, BK=32.
#define APITCH 80
#define BPITCH 272
template<int MODE, bool STATS>
__global__ void __launch_bounds__(256,2) gemm_hmma(
    const float* __restrict__ A, const float* __restrict__ A1,
    const float* __restrict__ Bm, const float* __restrict__ bias,
    float* __restrict__ C, int Kd, int Nd, int lda,
    size_t sA, size_t sB, size_t sC)
{
    __shared__ __align__(16) uint8_t sAhi[128*APITCH];
    __shared__ __align__(16) uint8_t sAlo[128*APITCH];
    __shared__ __align__(16) uint8_t sBhi[32*BPITCH];
    __shared__ __align__(16) uint8_t sBlo[32*BPITCH];
    __shared__ float sred[256];

    const int tid = threadIdx.x;
    const int lane = tid & 31, wid = tid >> 5;
    const int warpm = wid & 3, warpn = wid >> 2;
    const int brow = blockIdx.y * 128;
    const int bcol = blockIdx.x * 128;
    A += sA*blockIdx.z; Bm += sB*blockIdx.z; C += sC*blockIdx.z;

    const uint32_t aHi = smem_u32(sAhi), aLo = smem_u32(sAlo);
    const uint32_t bHi = smem_u32(sBhi), bLo = smem_u32(sBlo);

    float d[2][8][4];
    #pragma unroll
    for (int i=0;i<2;i++)
        #pragma unroll
        for (int j=0;j<8;j++)
            #pragma unroll
            for (int q=0;q<4;q++) d[i][j][q] = 0.f;

    const int nch = (Kd + 31) >> 5;
    const bool vec = ((lda & 3) == 0) && ((Kd & 31) == 0);

    for (int kc = 0; kc < nch; kc++){
        // ---- stage A: thread = (row, k-half of 16) ----
        {
            const int r = tid >> 1;
            const int kh = (tid & 1) * 16;
            float av[16];
            if (MODE == 2){
                const float* S = ((kc < 4) ? A : A1) + (size_t)(brow+r)*128 + (kc & 3)*32 + kh;
                #pragma unroll
                for (int q=0;q<4;q++) *reinterpret_cast<float4*>(&av[q*4]) =
                    *reinterpret_cast<const float4*>(S + q*4);
            } else if (MODE == 1 || vec){
                const float* S = A + (size_t)(brow+r)*lda + kc*32 + kh;
                #pragma unroll
                for (int q=0;q<4;q++) *reinterpret_cast<float4*>(&av[q*4]) =
                    *reinterpret_cast<const float4*>(S + q*4);
            } else {
                #pragma unroll
                for (int j=0;j<16;j++){
                    const int k = kc*32 + kh + j;
                    av[j] = (k < Kd) ? A[(size_t)(brow+r)*lda + k] : 0.f;
                }
            }
            if (MODE == 1){
                #pragma unroll
                for (int j=0;j<16;j++){
                    const int k = kc*32 + kh + j;
                    av[j] = siluf(av[j]*g_scale[k] + g_shift[k]);
                }
            }
            uint4 h0,l0,h1,l1;
            split8(&av[0], h0, l0);
            split8(&av[8], h1, l1);
            const uint32_t off = (uint32_t)r*APITCH + (uint32_t)kh*2;
            *reinterpret_cast<uint4*>(sAhi + off)      = h0;
            *reinterpret_cast<uint4*>(sAhi + off + 16) = h1;
            *reinterpret_cast<uint4*>(sAlo + off)      = l0;
            *reinterpret_cast<uint4*>(sAlo + off + 16) = l1;
        }
        // ---- stage B: thread = (k-row, 16-n segment) ----
        {
            const int kr = tid >> 3;
            const int ns = (tid & 7) * 16;
            const int gk = kc*32 + kr;
            float bv[16];
            if (gk < Kd){
                const float* S = Bm + (size_t)gk*Nd + bcol + ns;
                #pragma unroll
                for (int q=0;q<4;q++) *reinterpret_cast<float4*>(&bv[q*4]) =
                    *reinterpret_cast<const float4*>(S + q*4);
            } else {
                #pragma unroll
                for (int j=0;j<16;j++) bv[j] = 0.f;
            }
            uint4 h0,l0,h1,l1;
            split8(&bv[0], h0, l0);
            split8(&bv[8], h1, l1);
            const uint32_t off = (uint32_t)kr*BPITCH + (uint32_t)ns*2;
            *reinterpret_cast<uint4*>(sBhi + off)      = h0;
            *reinterpret_cast<uint4*>(sBhi + off + 16) = h1;
            *reinterpret_cast<uint4*>(sBlo + off)      = l0;
            *reinterpret_cast<uint4*>(sBlo + off + 16) = l1;
        }
        __syncthreads();

        // ---- compute: 2 k16-steps ----
        #pragma unroll
        for (int ks=0; ks<2; ks++){
            uint32_t ah[2][4], al[2][4];
            #pragma unroll
            for (int mb=0; mb<2; mb++){
                const uint32_t ao = (uint32_t)(warpm*32 + mb*16 + (lane & 15))*APITCH
                                  + ks*32 + ((lane >> 4)*16);
                ldsm4(ah[mb], aHi + ao);
                ldsm4(al[mb], aLo + ao);
            }
            #pragma unroll
            for (int np=0; np<4; np++){
                const int n0 = warpn*64 + np*16;
                const uint32_t bo = (uint32_t)(ks*16 + (lane & 15))*BPITCH
                                  + (uint32_t)n0*2 + ((lane >> 4)*16);
                uint32_t bh[4], bl[4];
                ldsm4t(bh, bHi + bo);
                ldsm4t(bl, bLo + bo);
                #pragma unroll
                for (int mb=0; mb<2; mb++){
                    mma16816(d[mb][np*2  ], ah[mb], bh[0], bh[1]);
                    mma16816(d[mb][np*2  ], al[mb], bh[0], bh[1]);
                    mma16816(d[mb][np*2  ], ah[mb], bl[0], bl[1]);
                    mma16816(d[mb][np*2+1], ah[mb], bh[2], bh[3]);
                    mma16816(d[mb][np*2+1], al[mb], bh[2], bh[3]);
                    mma16816(d[mb][np*2+1], ah[mb], bl[2], bl[3]);
                }
            }
        }
        __syncthreads();
    }

    // ---- epilogue: bias + store ----
    #pragma unroll
    for (int mb=0; mb<2; mb++){
        #pragma unroll
        for (int nb=0; nb<8; nb++){
            const int m = brow + warpm*32 + mb*16 + (lane >> 2);
            const int n = bcol + warpn*64 + nb*8 + (lane & 3)*2;
            float b0 = 0.f, b1 = 0.f;
            if (bias){ b0 = bias[n]; b1 = bias[n+1]; }
            d[mb][nb][0] += b0; d[mb][nb][1] += b1;
            d[mb][nb][2] += b0; d[mb][nb][3] += b1;
            *reinterpret_cast<float2*>(C + (size_t)m*Nd + n) =
                make_float2(d[mb][nb][0], d[mb][nb][1]);
            *reinterpret_cast<float2*>(C + (size_t)(m+8)*Nd + n) =
                make_float2(d[mb][nb][2], d[mb][nb][3]);
        }
    }

    // ---- fused column stats ----
    if (STATS){
        sred[tid] = 0.f;
        __syncthreads();
        float s[16], q[16];
        #pragma unroll
        for (int i=0;i<16;i++){ s[i]=0.f; q[i]=0.f; }
        #pragma unroll
        for (int mb=0; mb<2; mb++)
            #pragma unroll
            for (int nb=0; nb<8; nb++){
                s[nb*2+0] += d[mb][nb][0] + d[mb][nb][2];
                s[nb*2+1] += d[mb][nb][1] + d[mb][nb][3];
                q[nb*2+0] += d[mb][nb][0]*d[mb][nb][0] + d[mb][nb][2]*d[mb][nb][2];
                q[nb*2+1] += d[mb][nb][1]*d[mb][nb][1] + d[mb][nb][3]*d[mb][nb][3];
            }
        #pragma unroll
        for (int off=4; off<32; off<<=1){
            #pragma unroll
            for (int i=0;i<16;i++){
                s[i] += __shfl_xor_sync(0xFFFFFFFFu, s[i], off);
                q[i] += __shfl_xor_sync(0xFFFFFFFFu, q[i], off);
            }
        }
        if (lane < 4){
            #pragma unroll
            for (int i=0;i<16;i++){
                const int col = warpn*64 + (i>>1)*8 + (lane & 3)*2 + (i & 1);
                atomicAdd(&sred[col], s[i]);
                atomicAdd(&sred[128+col], q[i]);
            }
        }
        __syncthreads();
        if (tid < 128){
            atomicAdd(&g_sum  [bcol + tid], sred[tid]);
            atomicAdd(&g_sumsq[bcol + tid], sred[128 + tid]);
        }
    }
}

// ================= spectral forward (HMMA) =================
// HS[b,k,h] += sum_v evecs_inv[b,k,v] * h[b,v,h]
// A = eigs[b, 1+V+v, :] stored [v][k] (k contiguous); B = Hb[v][h].
// Both operands trans-staged; M = spectral k (128), N = h (128), reduce over v.
template<int DUMMY>
__global__ void __launch_bounds__(256,2) spec_hmma(
    const float* __restrict__ eigs, const float* __restrict__ Hb, float* __restrict__ HS)
{
    __shared__ __align__(16) uint8_t sAhi[32*BPITCH];
    __shared__ __align__(16) uint8_t sAlo[32*BPITCH];
    __shared__ __align__(16) uint8_t sBhi[32*BPITCH];
    __shared__ __align__(16) uint8_t sBlo[32*BPITCH];

    const int b   = blockIdx.z;
    const int seg = blockIdx.x;
    const float* A  = eigs + ((size_t)b*(2*V_+1) + 1 + V_) * K_;
    const float* Bm = Hb   + (size_t)b*V_*H_;

    const int tid = threadIdx.x;
    const int lane = tid & 31, wid = tid >> 5;
    const int warpm = wid & 3, warpn = wid >> 2;

    const uint32_t aHi = smem_u32(sAhi), aLo = smem_u32(sAlo);
    const uint32_t bHi = smem_u32(sBhi), bLo = smem_u32(sBlo);

    float d[2][8][4];
    #pragma unroll
    for (int i=0;i<2;i++)
        #pragma unroll
        for (int j=0;j<8;j++)
            #pragma unroll
            for (int q=0;q<4;q++) d[i][j][q] = 0.f;

    const int v0 = seg * (V_/SPLITV);
    for (int vc = 0; vc < V_/SPLITV/32; vc++){
        const int vr = tid >> 3;
        const int cs = (tid & 7) * 16;
        const int v = v0 + vc*32 + vr;
        // stage A [v][k]
        {
            float av[16];
            const float* S = A + (size_t)v*K_ + cs;
            #pragma unroll
            for (int q2=0;q2<4;q2++) *reinterpret_cast<float4*>(&av[q2*4]) =
                *reinterpret_cast<const float4*>(S + q2*4);
            uint4 h0,l0,h1,l1;
            split8(&av[0], h0, l0);
            split8(&av[8], h1, l1);
            const uint32_t off = (uint32_t)vr*BPITCH + (uint32_t)cs*2;
            *reinterpret_cast<uint4*>(sAhi + off)      = h0;
            *reinterpret_cast<uint4*>(sAhi + off + 16) = h1;
            *reinterpret_cast<uint4*>(sAlo + off)      = l0;
            *reinterpret_cast<uint4*>(sAlo + off + 16) = l1;
        }
        // stage B [v][h]
        {
            float bv[16];
            const float* S = Bm + (size_t)v*H_ + cs;
            #pragma unroll
            for (int q2=0;q2<4;q2++) *reinterpret_cast<float4*>(&bv[q2*4]) =
                *reinterpret_cast<const float4*>(S + q2*4);
            uint4 h0,l0,h1,l1;
            split8(&bv[0], h0, l0);
            split8(&bv[8], h1, l1);
            const uint32_t off = (uint32_t)vr*BPITCH + (uint32_t)cs*2;
            *reinterpret_cast<uint4*>(sBhi + off)      = h0;
            *reinterpret_cast<uint4*>(sBhi + off + 16) = h1;
            *reinterpret_cast<uint4*>(sBlo + off)      = l0;
            *reinterpret_cast<uint4*>(sBlo + off + 16) = l1;
        }
        __syncthreads();

        #pragma unroll
        for (int ks=0; ks<2; ks++){
            uint32_t ah[2][4], al[2][4];
            #pragma unroll
            for (int mb=0; mb<2; mb++){
                // A-frag via trans: row = v, col = m (spectral k)
                const uint32_t ao = (uint32_t)(ks*16 + (lane & 7) + ((lane >> 4)*8))*BPITCH
                                  + (uint32_t)(warpm*32 + mb*16)*2 + (((lane >> 3) & 1)*16);
                ldsm4t(ah[mb], aHi + ao);
                ldsm4t(al[mb], aLo + ao);
            }
            #pragma unroll
            for (int np=0; np<4; np++){
                const int n0 = warpn*64 + np*16;
                const uint32_t bo = (uint32_t)(ks*16 + (lane & 15))*BPITCH
                                  + (uint32_t)n0*2 + ((lane >> 4)*16);
                uint32_t bh[4], bl[4];
                ldsm4t(bh, bHi + bo);
                ldsm4t(bl, bLo + bo);
                #pragma unroll
                for (int mb=0; mb<2; mb++){
                    mma16816(d[mb][np*2  ], ah[mb], bh[0], bh[1]);
                    mma16816(d[mb][np*2  ], al[mb], bh[0], bh[1]);
                    mma16816(d[mb][np*2  ], ah[mb], bl[0], bl[1]);
                    mma16816(d[mb][np*2+1], ah[mb], bh[2], bh[3]);
                    mma16816(d[mb][np*2+1], al[mb], bh[2], bh[3]);
                    mma16816(d[mb][np*2+1], ah[mb], bl[2], bl[3]);
                }
            }
        }
        __syncthreads();
    }

    float* Cb = HS + (size_t)b*K_*H_;
    #pragma unroll
    for (int mb=0; mb<2; mb++)
        #pragma unroll
        for (int nb=0; nb<8; nb++){
            const int m = warpm*32 + mb*16 + (lane >> 2);
            const int n = warpn*64 + nb*8 + (lane & 3)*2;
            red_add_v2(Cb + (size_t)m*H_ + n,     d[mb][nb][0], d[mb][nb][1]);
            red_add_v2(Cb + (size_t)(m+8)*H_ + n, d[mb][nb][2], d[mb][nb][3]);
        }
}

// HS[b,k,h] *= exp(-eig[b,k] * max(prop_time[l,h],1e-6))
__global__ void coeff_mul(const float* __restrict__ eigs, const float* __restrict__ pt,
                          float* __restrict__ HS, int l)
{
    const int b = blockIdx.y, k = blockIdx.x, h = threadIdx.x;
    const float ev = eigs[(size_t)b*(2*V_+1)*K_ + k];
    const float t  = fmaxf(pt[l*H_ + h], 1e-6f);
    HS[((size_t)b*K_ + k)*H_ + h] *= __expf(-ev*t);
}

__global__ void finalize_bn(const float* __restrict__ g, const float* __restrict__ be, float Rinv){
    const int c = threadIdx.x;
    const float m   = g_sum[c]*Rinv;
    const float var = g_sumsq[c]*Rinv - m*m;
    const float sc  = g[c] * rsqrtf(var + EPSF);
    g_scale[c] = sc;
    g_shift[c] = be[c] - m*sc;
}

// ---------------- message + scatter-add ----------------
__global__ void msg_scatter(const float* __restrict__ Y2, const int* __restrict__ vid,
                            float* __restrict__ Hout)
{
    const int sub = threadIdx.x >> 5;
    const int c4  = (threadIdx.x & 31) * 4;
    const int e0  = blockIdx.x * 32 + sub * 8;
    const float s0=g_scale[c4],   s1=g_scale[c4+1],   s2=g_scale[c4+2],   s3=g_scale[c4+3];
    const float t0=g_shift[c4],   t1=g_shift[c4+1],   t2=g_shift[c4+2],   t3=g_shift[c4+3];
    const float u0=g_scale[128+c4],u1=g_scale[129+c4],u2=g_scale[130+c4],u3=g_scale[131+c4];
    const float w0=g_shift[128+c4],w1=g_shift[129+c4],w2=g_shift[130+c4],w3=g_shift[131+c4];
    #pragma unroll
    for (int i=0;i<8;i++){
        const int e = e0 + i;
        float4 f = *reinterpret_cast<const float4*>(Y2 + (size_t)e*256 + c4);
        float4 c = *reinterpret_cast<const float4*>(Y2 + (size_t)e*256 + 128 + c4);
        float m0 = (1.f/(1.f+__expf(-(f.x*s0+t0)))) * softplusf(c.x*u0+w0);
        float m1 = (1.f/(1.f+__expf(-(f.y*s1+t1)))) * softplusf(c.y*u1+w1);
        float m2 = (1.f/(1.f+__expf(-(f.z*s2+t2)))) * softplusf(c.z*u2+w2);
        float m3 = (1.f/(1.f+__expf(-(f.w*s3+t3)))) * softplusf(c.w*u3+w3);
        const int v = vid[e];
        red_add_v4(Hout + (size_t)v*128 + c4, m0, m1, m2, m3);
    }
}

// h += bn(Y)
__global__ void h_update(float* __restrict__ H, const float* __restrict__ Y){
    const size_t i = (size_t)blockIdx.x*256 + threadIdx.x;
    const int c = (int)(i & 127);
    H[i] += Y[i]*g_scale[c] + g_shift[c];
}

// out[b] += mean_v( silu(bn(Yo)) . wo2 + bo2 )
__global__ void out_reduce(const float* __restrict__ Yo, const float* __restrict__ wo2,
                           const float* __restrict__ bo2, float* __restrict__ out)
{
    const int warp = threadIdx.x >> 5, lane = threadIdx.x & 31;
    const long n = (long)blockIdx.x*8 + warp;
    float s = 0.f;
    #pragma unroll
    for (int j=0;j<4;j++){
        const int h = lane + j*32;
        float x = Yo[(size_t)n*128 + h]*g_scale[h] + g_shift[h];
        x = siluf(x);
        s += x * wo2[h];
    }
    #pragma unroll
    for (int o=16;o>0;o>>=1) s += __shfl_xor_sync(0xFFFFFFFFu, s, o);
    if (lane == 0){
        const int b = (int)(n >> 11);
        atomicAdd(&out[b], (s + bo2[0]) * (1.f/(float)V_));
    }
}

// ---------------- launcher ----------------
extern "C" void kernel_launch(void* const* d_in, const int* in_sizes, int n_in,
                              void* d_out, int out_size)
{
    const float* chem = (const float*)d_in[0];
    const int*   vid  = (const int*  )d_in[1];
    const float* eigs = (const float*)d_in[2];
    const float* w1   = (const float*)d_in[3];
    const float* b1   = (const float*)d_in[4];
    const float* g1   = (const float*)d_in[5];
    const float* be1  = (const float*)d_in[6];
    const float* w2   = (const float*)d_in[7];
    const float* b2   = (const float*)d_in[8];
    const float* g2   = (const float*)d_in[9];
    const float* be2  = (const float*)d_in[10];
    const float* ptim = (const float*)d_in[11];
    const float* pw1  = (const float*)d_in[12];
    const float* pb1  = (const float*)d_in[13];
    const float* pg1  = (const float*)d_in[14];
    const float* pbe1 = (const float*)d_in[15];
    const float* pw2  = (const float*)d_in[16];
    const float* pb2  = (const float*)d_in[17];
    const float* pg2  = (const float*)d_in[18];
    const float* pbe2 = (const float*)d_in[19];
    const float* wo1  = (const float*)d_in[20];
    const float* bo1  = (const float*)d_in[21];
    const float* go1  = (const float*)d_in[22];
    const float* beo1 = (const float*)d_in[23];
    const float* wo2  = (const float*)d_in[24];
    const float* bo2  = (const float*)d_in[25];
    float* outp = (float*)d_out;

    void* p;
    float *pY1,*pY2,*pH,*pHP,*pHS,*pYa,*pYb;
    cudaGetSymbolAddress(&p, g_Y1); pY1=(float*)p;
    cudaGetSymbolAddress(&p, g_Y2); pY2=(float*)p;
    cudaGetSymbolAddress(&p, g_H ); pH =(float*)p;
    cudaGetSymbolAddress(&p, g_HP); pHP=(float*)p;
    cudaGetSymbolAddress(&p, g_HS); pHS=(float*)p;
    cudaGetSymbolAddress(&p, g_Ya); pYa=(float*)p;
    cudaGetSymbolAddress(&p, g_Yb); pYb=(float*)p;

    zero_kernel<<<1, 64>>>(outp, 64);

    // ---- chem MLP stage 1: Y1 = chem @ w1 + b1 (stats fused) ----
    zero_stats<<<1,256>>>();
    gemm_hmma<0,true><<<dim3(1, E_/128, 1), 256>>>(
        chem, nullptr, w1, b1, pY1, CF_, 128, CF_, 0, 0, 0);
    finalize_bn<<<1,128>>>(g1, be1, 1.f/(float)E_);

    // ---- stage 2: Y2 = silu(bn(Y1)) @ w2 + b2 (stats fused) ----
    zero_stats<<<1,256>>>();
    gemm_hmma<1,true><<<dim3(2, E_/128, 1), 256>>>(
        pY1, nullptr, w2, b2, pY2, 128, 256, 128, 0, 0, 0);
    finalize_bn<<<1,256>>>(g2, be2, 1.f/(float)E_);

    // ---- message + segment_sum ----
    zero_kernel<<<(unsigned)(((size_t)N_*H_)/256), 256>>>(pH, (size_t)N_*H_);
    msg_scatter<<<E_/32, 128>>>(pY2, vid, pH);

    // ---- propagation layers ----
    for (int l = 0; l < L_; l++){
        zero_kernel<<<(B_*K_*H_+255)/256, 256>>>(pHS, (size_t)B_*K_*H_);
        spec_hmma<0><<<dim3(SPLITV, 1, B_), 256>>>(eigs, pH, pHS);
        coeff_mul<<<dim3(K_,B_), H_>>>(eigs, ptim, pHS, l);
        // h_prop = evecs @ (coeff * h_spec), batched over B
        gemm_hmma<0,false><<<dim3(1, V_/128, B_), 256>>>(
            eigs + K_, nullptr, pHS, nullptr, pHP, 128, 128, 128,
            (size_t)(2*V_+1)*K_, (size_t)K_*H_, (size_t)V_*H_);
        // z-MLP stage 1: Ya = [h, h_prop] @ pw1[l] + pb1[l]
        zero_stats<<<1,256>>>();
        gemm_hmma<2,true><<<dim3(1, N_/128, 1), 256>>>(
            pH, pHP, pw1 + (size_t)l*2*H_*H_, pb1 + l*H_, pYa, 256, 128, 128, 0, 0, 0);
        finalize_bn<<<1,128>>>(pg1 + l*H_, pbe1 + l*H_, 1.f/(float)N_);
        // z-MLP stage 2: Yb = silu(bn(Ya)) @ pw2[l] + pb2[l]
        zero_stats<<<1,256>>>();
        gemm_hmma<1,true><<<dim3(1, N_/128, 1), 256>>>(
            pYa, nullptr, pw2 + (size_t)l*H_*H_, pb2 + l*H_, pYb, 128, 128, 128, 0, 0, 0);
        finalize_bn<<<1,128>>>(pg2 + l*H_, pbe2 + l*H_, 1.f/(float)N_);
        h_update<<<(unsigned)(((size_t)N_*H_)/256), 256>>>(pH, pYb);
    }

    // ---- output head ----
    zero_stats<<<1,256>>>();
    gemm_hmma<0,true><<<dim3(1, N_/128, 1), 256>>>(
        pH, nullptr, wo1, bo1, pYa, 128, 128, 128, 0, 0, 0);
    finalize_bn<<<1,128>>>(go1, beo1, 1.f/(float)N_);
    out_reduce<<<N_/8, 256>>>(pYa, wo2, bo2, outp);
}

// round 5
// speedup vs baseline: 1.9734x; 1.1032x over previous
#include <cuda_runtime.h>
#include <cuda_bf16.h>
#include <cstdint>

// ---------------- problem constants ----------------
#define B_   64
#define V_   2048
#define K_   128
#define H_   128
#define N_   (B_*V_)
#define E_   1048576
#define CF_  47
#define L_   3
#define EPSF 1e-5f
#define SPLITV 4

// ---------------- scratch ----------------
__device__ float g_Y1[(size_t)E_*H_];
__device__ float g_Y2[(size_t)E_*2*H_];
__device__ float g_H [(size_t)N_*H_];
__device__ float g_HS[(size_t)B_*K_*H_];
__device__ float g_Ya[(size_t)N_*H_];
__device__ float g_Yb[(size_t)N_*H_];
__device__ float g_sum[256], g_sumsq[256], g_scale[256], g_shift[256];
// pre-split bf16 operands
__device__ __nv_bfloat16 w1s_hi[64*128],        w1s_lo[64*128];
__device__ __nv_bfloat16 w2s_hi[128*256],       w2s_lo[128*256];
__device__ __nv_bfloat16 pw1s_hi[3*256*128],    pw1s_lo[3*256*128];
__device__ __nv_bfloat16 pw2s_hi[3*128*128],    pw2s_lo[3*128*128];
__device__ __nv_bfloat16 wo1s_hi[128*128],      wo1s_lo[128*128];
__device__ __nv_bfloat16 g_evhi[(size_t)B_*V_*K_], g_evlo[(size_t)B_*V_*K_];
__device__ __nv_bfloat16 g_eihi[(size_t)B_*V_*K_], g_eilo[(size_t)B_*V_*K_];
__device__ __nv_bfloat16 g_hshi[(size_t)B_*K_*H_], g_hslo[(size_t)B_*K_*H_];
__device__ __nv_bfloat16 g_hhi [(size_t)N_*H_],    g_hlo [(size_t)N_*H_];
__device__ __nv_bfloat16 g_hphi[(size_t)N_*H_],    g_hplo[(size_t)N_*H_];

// ---------------- helpers ----------------
__device__ __forceinline__ float siluf(float x){ return x * (1.f/(1.f+__expf(-x))); }
__device__ __forceinline__ float softplusf(float x){ return x > 20.f ? x : log1pf(__expf(x)); }
__device__ __forceinline__ void red_add_v4(float* a, float x, float y, float z, float w){
    asm volatile("red.global.add.v4.f32 [%0], {%1,%2,%3,%4};"
                 :: "l"(a), "f"(x), "f"(y), "f"(z), "f"(w) : "memory");
}
__device__ __forceinline__ void red_add_v2(float* a, float x, float y){
    asm volatile("red.global.add.v2.f32 [%0], {%1,%2};" :: "l"(a), "f"(x), "f"(y) : "memory");
}
__device__ __forceinline__ uint32_t smem_u32(const void* p){
    uint32_t a;
    asm("{ .reg .u64 t; cvta.to.shared.u64 t, %1; cvt.u32.u64 %0, t; }" : "=r"(a) : "l"(p));
    return a;
}
__device__ __forceinline__ void cpasync16(uint32_t s, const void* g){
    asm volatile("cp.async.ca.shared.global [%0], [%1], 16;" :: "r"(s), "l"(g));
}
#define CP_COMMIT() asm volatile("cp.async.commit_group;")
#define CP_WAIT0()  asm volatile("cp.async.wait_group 0;")

__device__ __forceinline__ void ldsm4(uint32_t* r, uint32_t addr){
    asm volatile("ldmatrix.sync.aligned.m8n8.x4.shared.b16 {%0,%1,%2,%3}, [%4];"
        : "=r"(r[0]),"=r"(r[1]),"=r"(r[2]),"=r"(r[3]) : "r"(addr));
}
__device__ __forceinline__ void ldsm4t(uint32_t* r, uint32_t addr){
    asm volatile("ldmatrix.sync.aligned.m8n8.x4.trans.shared.b16 {%0,%1,%2,%3}, [%4];"
        : "=r"(r[0]),"=r"(r[1]),"=r"(r[2]),"=r"(r[3]) : "r"(addr));
}
__device__ __forceinline__ void mma16816(float* d, const uint32_t* a, uint32_t b0, uint32_t b1){
    asm volatile("mma.sync.aligned.m16n8k16.row.col.f32.bf16.bf16.f32 "
        "{%0,%1,%2,%3}, {%4,%5,%6,%7}, {%8,%9}, {%0,%1,%2,%3};"
        : "+f"(d[0]),"+f"(d[1]),"+f"(d[2]),"+f"(d[3])
        : "r"(a[0]),"r"(a[1]),"r"(a[2]),"r"(a[3]), "r"(b0),"r"(b1));
}

__device__ __forceinline__ void split8(const float* f, uint4& hi, uint4& lo){
    unsigned h[4], l[4];
    #pragma unroll
    for (int p=0;p<4;p++){
        float2 a = make_float2(f[2*p], f[2*p+1]);
        __nv_bfloat162 bh = __float22bfloat162_rn(a);
        float hx = __bfloat162float(bh.x), hy = __bfloat162float(bh.y);
        float2 rz = make_float2(a.x - hx, a.y - hy);
        __nv_bfloat162 bl = __float22bfloat162_rn(rz);
        h[p] = *reinterpret_cast<unsigned*>(&bh);
        l[p] = *reinterpret_cast<unsigned*>(&bl);
    }
    hi = make_uint4(h[0],h[1],h[2],h[3]);
    lo = make_uint4(l[0],l[1],l[2],l[3]);
}
__device__ __forceinline__ void split1(float v, __nv_bfloat16& hi, __nv_bfloat16& lo){
    hi = __float2bfloat16_rn(v);
    lo = __float2bfloat16_rn(v - __bfloat162float(hi));
}

__global__ void zero_kernel(float* __restrict__ p, size_t n){
    size_t i = (size_t)blockIdx.x*blockDim.x + threadIdx.x;
    if (i < n) p[i] = 0.f;
}
__global__ void zero_stats(){ g_sum[threadIdx.x]=0.f; g_sumsq[threadIdx.x]=0.f; }

// ---------------- prep: split kernels ----------------
__global__ void split_mat(const float* __restrict__ src, __nv_bfloat16* __restrict__ hi,
                          __nv_bfloat16* __restrict__ lo, size_t n){
    size_t i = (size_t)blockIdx.x*256 + threadIdx.x;
    if (i < n){ __nv_bfloat16 h, l; split1(src[i], h, l); hi[i]=h; lo[i]=l; }
}
__global__ void split_w1(const float* __restrict__ w1){
    int i = blockIdx.x*256 + threadIdx.x;           // 64*128
    int k = i >> 7, n = i & 127;
    float v = (k < CF_) ? w1[k*128 + n] : 0.f;
    __nv_bfloat16 h, l; split1(v, h, l);
    w1s_hi[i]=h; w1s_lo[i]=l;
}
__global__ void split_eigs_k(const float* __restrict__ eigs){
    size_t i = (size_t)blockIdx.x*256 + threadIdx.x;   // over 64*2048*128
    size_t b = i >> 18, rem = i & 0x3FFFF;
    const float* base = eigs + (b*(size_t)(2*V_+1) + 1)*K_;
    __nv_bfloat16 h, l;
    split1(base[rem], h, l);                 g_evhi[i]=h; g_evlo[i]=l;
    split1(base[(size_t)V_*K_ + rem], h, l); g_eihi[i]=h; g_eilo[i]=l;
}

// ================= pipelined HMMA split-bf16 GEMM =================
// ASRC 0: A fp32 plain, guarded scalar loads (GEMM1, Kd=47)
// ASRC 1: A fp32, silu(A*scale+shift), Kd=128, lda%4==0
// ASRC 3: A pre-split bf16 (Ahi/Alo), row stride lda
// ASRC 4: A concat pre-split: kc<4 -> Ahi/Alo, else A2hi/A2lo (Kd=256, rows of 128)
// B always pre-split bf16 [k][n], rows padded to 32-multiples.
// OUTSPLIT: write Chi/Clo bf16 instead of fp32 C.
#define APITCH 80
#define BPITCH 272
#define SMBUF  37888     // per buffer: Ahi 10240 | Alo 10240 | Bhi 8704 | Blo 8704
template<int ASRC, bool STATS, bool OUTSPLIT>
__global__ void __launch_bounds__(256,2) gemm5(
    const float* __restrict__ Af,
    const __nv_bfloat16* __restrict__ Ahi, const __nv_bfloat16* __restrict__ Alo,
    const __nv_bfloat16* __restrict__ A2hi, const __nv_bfloat16* __restrict__ A2lo,
    const __nv_bfloat16* __restrict__ Bhi, const __nv_bfloat16* __restrict__ Blo,
    const float* __restrict__ bias, float* __restrict__ C,
    __nv_bfloat16* __restrict__ Chi, __nv_bfloat16* __restrict__ Clo,
    int Kd, int Nd, int lda,
    size_t sAs, size_t sBs, size_t sC)
{
    extern __shared__ __align__(16) uint8_t smem[];
    const uint32_t sb = smem_u32(smem);
    const int tid = threadIdx.x;
    const int lane = tid & 31, wid = tid >> 5;
    const int warpm = wid & 3, warpn = wid >> 2;
    const int brow = blockIdx.y * 128;
    const int bcol = blockIdx.x * 128;
    const int bz   = blockIdx.z;
    Ahi += sAs*bz; Alo += sAs*bz; Bhi += sBs*bz; Blo += sBs*bz;
    if (C)   C   += sC*bz;
    if (Chi){ Chi += sC*bz; Clo += sC*bz; }

    const int nch = (Kd + 31) >> 5;

    // staging index precompute
    const int ar = tid >> 1, akh = (tid & 1) * 16;      // A: row, k-sub
    const int bkr = tid >> 3, bns = (tid & 7) * 16;     // B: k-row, n-seg

    // ---- staging lambdas ----
    auto stageB = [&](int kc, int buf){
        const int gk = kc*32 + bkr;
        const uint32_t dst = sb + buf*SMBUF + 20480 + bkr*BPITCH + bns*2;
        const size_t so = (size_t)gk*Nd + bcol + bns;
        cpasync16(dst,          Bhi + so);
        cpasync16(dst + 16,     Bhi + so + 8);
        cpasync16(dst + 8704,      Blo + so);
        cpasync16(dst + 8704 + 16, Blo + so + 8);
    };
    auto stageA_async = [&](int kc, int buf){
        const __nv_bfloat16 *hi, *lo;
        int col, ldaA;
        if (ASRC == 4){
            if (kc < 4){ hi = Ahi; lo = Alo; } else { hi = A2hi; lo = A2lo; }
            col = (kc & 3)*32 + akh; ldaA = 128;
        } else { hi = Ahi; lo = Alo; col = kc*32 + akh; ldaA = lda; }
        const size_t so = (size_t)(brow + ar)*ldaA + col;
        const uint32_t dst = sb + buf*SMBUF + ar*APITCH + akh*2;
        cpasync16(dst,            hi + so);
        cpasync16(dst + 16,       hi + so + 8);
        cpasync16(dst + 10240,      lo + so);
        cpasync16(dst + 10240 + 16, lo + so + 8);
    };
    auto loadA_f32 = [&](int kc, float* av){
        if (ASRC == 1){
            const float* S = Af + (size_t)(brow+ar)*lda + kc*32 + akh;
            #pragma unroll
            for (int q=0;q<4;q++) *reinterpret_cast<float4*>(&av[q*4]) =
                *reinterpret_cast<const float4*>(S + q*4);
        } else {
            #pragma unroll
            for (int j=0;j<16;j++){
                const int k = kc*32 + akh + j;
                av[j] = (k < Kd) ? Af[(size_t)(brow+ar)*lda + k] : 0.f;
            }
        }
    };
    auto storeA_f32 = [&](int kc, int buf, float* av){
        if (ASRC == 1){
            #pragma unroll
            for (int j=0;j<16;j++){
                const int k = kc*32 + akh + j;
                av[j] = siluf(av[j]*g_scale[k] + g_shift[k]);
            }
        }
        uint4 h0,l0,h1,l1;
        split8(&av[0], h0, l0);
        split8(&av[8], h1, l1);
        uint8_t* base = smem + buf*SMBUF + ar*APITCH + akh*2;
        *reinterpret_cast<uint4*>(base)          = h0;
        *reinterpret_cast<uint4*>(base + 16)     = h1;
        *reinterpret_cast<uint4*>(base + 10240)      = l0;
        *reinterpret_cast<uint4*>(base + 10240 + 16) = l1;
    };

    constexpr bool A_F32 = (ASRC == 0) || (ASRC == 1);

    float d[2][8][4];
    #pragma unroll
    for (int i=0;i<2;i++)
        #pragma unroll
        for (int j=0;j<8;j++)
            #pragma unroll
            for (int q=0;q<4;q++) d[i][j][q] = 0.f;

    // ---- prologue: stage chunk 0 into buf 0 ----
    float av[16];
    stageB(0, 0);
    if (A_F32){ loadA_f32(0, av); storeA_f32(0, 0, av); }
    else       stageA_async(0, 0);
    CP_COMMIT();
    CP_WAIT0();
    __syncthreads();

    for (int kc = 0; kc < nch; kc++){
        const int cur = kc & 1, nxt = cur ^ 1;
        const bool more = (kc + 1 < nch);
        if (more){
            stageB(kc+1, nxt);
            if (!A_F32) stageA_async(kc+1, nxt);
            CP_COMMIT();
            if (A_F32) loadA_f32(kc+1, av);
        }
        // ---- compute on buf cur ----
        const uint32_t aHi = sb + cur*SMBUF;
        const uint32_t aLo = aHi + 10240;
        const uint32_t bHi = aHi + 20480;
        const uint32_t bLo = aHi + 29184;
        #pragma unroll
        for (int ks=0; ks<2; ks++){
            uint32_t ah[2][4], al[2][4];
            #pragma unroll
            for (int mb=0; mb<2; mb++){
                const uint32_t ao = (uint32_t)(warpm*32 + mb*16 + (lane & 15))*APITCH
                                  + ks*32 + ((lane >> 4)*16);
                ldsm4(ah[mb], aHi + ao);
                ldsm4(al[mb], aLo + ao);
            }
            #pragma unroll
            for (int np=0; np<4; np++){
                const int n0 = warpn*64 + np*16;
                const uint32_t bo = (uint32_t)(ks*16 + (lane & 15))*BPITCH
                                  + (uint32_t)n0*2 + ((lane >> 4)*16);
                uint32_t bh[4], bl[4];
                ldsm4t(bh, bHi + bo);
                ldsm4t(bl, bLo + bo);
                #pragma unroll
                for (int mb=0; mb<2; mb++){
                    mma16816(d[mb][np*2  ], ah[mb], bh[0], bh[1]);
                    mma16816(d[mb][np*2  ], al[mb], bh[0], bh[1]);
                    mma16816(d[mb][np*2  ], ah[mb], bl[0], bl[1]);
                    mma16816(d[mb][np*2+1], ah[mb], bh[2], bh[3]);
                    mma16816(d[mb][np*2+1], al[mb], bh[2], bh[3]);
                    mma16816(d[mb][np*2+1], ah[mb], bl[2], bl[3]);
                }
            }
        }
        if (more){
            if (A_F32) storeA_f32(kc+1, nxt, av);
            CP_WAIT0();
        }
        __syncthreads();
    }

    // ---- epilogue ----
    #pragma unroll
    for (int mb=0; mb<2; mb++){
        #pragma unroll
        for (int nb=0; nb<8; nb++){
            const int m = brow + warpm*32 + mb*16 + (lane >> 2);
            const int n = bcol + warpn*64 + nb*8 + (lane & 3)*2;
            float b0 = 0.f, b1 = 0.f;
            if (bias){ b0 = bias[n]; b1 = bias[n+1]; }
            d[mb][nb][0] += b0; d[mb][nb][1] += b1;
            d[mb][nb][2] += b0; d[mb][nb][3] += b1;
            if (OUTSPLIT){
                __nv_bfloat162 h2 = __float22bfloat162_rn(make_float2(d[mb][nb][0], d[mb][nb][1]));
                __nv_bfloat162 l2 = __float22bfloat162_rn(make_float2(
                    d[mb][nb][0]-__bfloat162float(h2.x), d[mb][nb][1]-__bfloat162float(h2.y)));
                *reinterpret_cast<__nv_bfloat162*>(Chi + (size_t)m*Nd + n) = h2;
                *reinterpret_cast<__nv_bfloat162*>(Clo + (size_t)m*Nd + n) = l2;
                __nv_bfloat162 h3 = __float22bfloat162_rn(make_float2(d[mb][nb][2], d[mb][nb][3]));
                __nv_bfloat162 l3 = __float22bfloat162_rn(make_float2(
                    d[mb][nb][2]-__bfloat162float(h3.x), d[mb][nb][3]-__bfloat162float(h3.y)));
                *reinterpret_cast<__nv_bfloat162*>(Chi + (size_t)(m+8)*Nd + n) = h3;
                *reinterpret_cast<__nv_bfloat162*>(Clo + (size_t)(m+8)*Nd + n) = l3;
            } else {
                *reinterpret_cast<float2*>(C + (size_t)m*Nd + n) =
                    make_float2(d[mb][nb][0], d[mb][nb][1]);
                *reinterpret_cast<float2*>(C + (size_t)(m+8)*Nd + n) =
                    make_float2(d[mb][nb][2], d[mb][nb][3]);
            }
        }
    }

    if (STATS){
        float* sred = reinterpret_cast<float*>(smem + 2*SMBUF);
        sred[tid] = 0.f;
        __syncthreads();
        float s[16], q[16];
        #pragma unroll
        for (int i=0;i<16;i++){ s[i]=0.f; q[i]=0.f; }
        #pragma unroll
        for (int mb=0; mb<2; mb++)
            #pragma unroll
            for (int nb=0; nb<8; nb++){
                s[nb*2+0] += d[mb][nb][0] + d[mb][nb][2];
                s[nb*2+1] += d[mb][nb][1] + d[mb][nb][3];
                q[nb*2+0] += d[mb][nb][0]*d[mb][nb][0] + d[mb][nb][2]*d[mb][nb][2];
                q[nb*2+1] += d[mb][nb][1]*d[mb][nb][1] + d[mb][nb][3]*d[mb][nb][3];
            }
        #pragma unroll
        for (int off=4; off<32; off<<=1){
            #pragma unroll
            for (int i=0;i<16;i++){
                s[i] += __shfl_xor_sync(0xFFFFFFFFu, s[i], off);
                q[i] += __shfl_xor_sync(0xFFFFFFFFu, q[i], off);
            }
        }
        if (lane < 4){
            #pragma unroll
            for (int i=0;i<16;i++){
                const int col = warpn*64 + (i>>1)*8 + (lane & 3)*2 + (i & 1);
                atomicAdd(&sred[col], s[i]);
                atomicAdd(&sred[128+col], q[i]);
            }
        }
        __syncthreads();
        if (tid < 128){
            atomicAdd(&g_sum  [bcol + tid], sred[tid]);
            atomicAdd(&g_sumsq[bcol + tid], sred[128 + tid]);
        }
    }
}

// ================= spectral forward (HMMA, pre-split inputs, pipelined) =================
// HS[b,k,h] += sum_v evinv[b,v,k] * H[b,v,h]; both staged v-major, trans ldsm.
#define SSMBUF 34816   // Ahi 8704 | Alo 8704 | Bhi 8704 | Blo 8704
__global__ void __launch_bounds__(256,2) spec5(float* __restrict__ HS)
{
    extern __shared__ __align__(16) uint8_t smem[];
    const uint32_t sb = smem_u32(smem);
    const int b   = blockIdx.z;
    const int seg = blockIdx.x;
    const __nv_bfloat16* Ahi = g_eihi + (size_t)b*V_*K_;
    const __nv_bfloat16* Alo = g_eilo + (size_t)b*V_*K_;
    const __nv_bfloat16* Bhi = g_hhi  + (size_t)b*V_*H_;
    const __nv_bfloat16* Blo = g_hlo  + (size_t)b*V_*H_;

    const int tid = threadIdx.x;
    const int lane = tid & 31, wid = tid >> 5;
    const int warpm = wid & 3, warpn = wid >> 2;
    const int vr = tid >> 3, cs = (tid & 7) * 16;
    const int v0 = seg * (V_/SPLITV);
    const int nch = V_/SPLITV/32;   // 16

    auto stage = [&](int vc, int buf){
        const int v = v0 + vc*32 + vr;
        const size_t soA = (size_t)v*K_ + cs;
        const size_t soB = (size_t)v*H_ + cs;
        const uint32_t base = sb + buf*SSMBUF + vr*BPITCH + cs*2;
        cpasync16(base,            Ahi + soA);
        cpasync16(base + 16,       Ahi + soA + 8);
        cpasync16(base + 8704,       Alo + soA);
        cpasync16(base + 8704 + 16,  Alo + soA + 8);
        cpasync16(base + 17408,      Bhi + soB);
        cpasync16(base + 17408 + 16, Bhi + soB + 8);
        cpasync16(base + 26112,      Blo + soB);
        cpasync16(base + 26112 + 16, Blo + soB + 8);
    };

    float d[2][8][4];
    #pragma unroll
    for (int i=0;i<2;i++)
        #pragma unroll
        for (int j=0;j<8;j++)
            #pragma unroll
            for (int q=0;q<4;q++) d[i][j][q] = 0.f;

    stage(0, 0);
    CP_COMMIT();
    CP_WAIT0();
    __syncthreads();

    for (int vc = 0; vc < nch; vc++){
        const int cur = vc & 1, nxt = cur ^ 1;
        const bool more = (vc + 1 < nch);
        if (more){ stage(vc+1, nxt); CP_COMMIT(); }

        const uint32_t aHi = sb + cur*SSMBUF;
        const uint32_t aLo = aHi + 8704;
        const uint32_t bHi = aHi + 17408;
        const uint32_t bLo = aHi + 26112;
        #pragma unroll
        for (int ks=0; ks<2; ks++){
            uint32_t ah[2][4], al[2][4];
            #pragma unroll
            for (int mb=0; mb<2; mb++){
                const uint32_t ao = (uint32_t)(ks*16 + (lane & 7) + ((lane >> 4)*8))*BPITCH
                                  + (uint32_t)(warpm*32 + mb*16)*2 + (((lane >> 3) & 1)*16);
                ldsm4t(ah[mb], aHi + ao);
                ldsm4t(al[mb], aLo + ao);
            }
            #pragma unroll
            for (int np=0; np<4; np++){
                const int n0 = warpn*64 + np*16;
                const uint32_t bo = (uint32_t)(ks*16 + (lane & 15))*BPITCH
                                  + (uint32_t)n0*2 + ((lane >> 4)*16);
                uint32_t bh[4], bl[4];
                ldsm4t(bh, bHi + bo);
                ldsm4t(bl, bLo + bo);
                #pragma unroll
                for (int mb=0; mb<2; mb++){
                    mma16816(d[mb][np*2  ], ah[mb], bh[0], bh[1]);
                    mma16816(d[mb][np*2  ], al[mb], bh[0], bh[1]);
                    mma16816(d[mb][np*2  ], ah[mb], bl[0], bl[1]);
                    mma16816(d[mb][np*2+1], ah[mb], bh[2], bh[3]);
                    mma16816(d[mb][np*2+1], al[mb], bh[2], bh[3]);
                    mma16816(d[mb][np*2+1], ah[mb], bl[2], bl[3]);
                }
            }
        }
        if (more) CP_WAIT0();
        __syncthreads();
    }

    float* Cb = HS + (size_t)b*K_*H_;
    #pragma unroll
    for (int mb=0; mb<2; mb++)
        #pragma unroll
        for (int nb=0; nb<8; nb++){
            const int m = warpm*32 + mb*16 + (lane >> 2);
            const int n = warpn*64 + nb*8 + (lane & 3)*2;
            red_add_v2(Cb + (size_t)m*H_ + n,     d[mb][nb][0], d[mb][nb][1]);
            red_add_v2(Cb + (size_t)(m+8)*H_ + n, d[mb][nb][2], d[mb][nb][3]);
        }
}

// HS -> coeff * HS, split to bf16 hi/lo
__global__ void coeff_mul_split(const float* __restrict__ eigs, const float* __restrict__ pt,
                                const float* __restrict__ HS, int l)
{
    const int b = blockIdx.y, k = blockIdx.x, h = threadIdx.x;
    const float ev = eigs[(size_t)b*(2*V_+1)*K_ + k];
    const float t  = fmaxf(pt[l*H_ + h], 1e-6f);
    const size_t i = ((size_t)b*K_ + k)*H_ + h;
    const float v = HS[i] * __expf(-ev*t);
    __nv_bfloat16 hi, lo; split1(v, hi, lo);
    g_hshi[i] = hi; g_hslo[i] = lo;
}

__global__ void finalize_bn(const float* __restrict__ g, const float* __restrict__ be, float Rinv){
    const int c = threadIdx.x;
    const float m   = g_sum[c]*Rinv;
    const float var = g_sumsq[c]*Rinv - m*m;
    const float sc  = g[c] * rsqrtf(var + EPSF);
    g_scale[c] = sc;
    g_shift[c] = be[c] - m*sc;
}

// ---------------- message + scatter-add ----------------
__global__ void msg_scatter(const float* __restrict__ Y2, const int* __restrict__ vid,
                            float* __restrict__ Hout)
{
    const int sub = threadIdx.x >> 5;
    const int c4  = (threadIdx.x & 31) * 4;
    const int e0  = blockIdx.x * 32 + sub * 8;
    const float s0=g_scale[c4],   s1=g_scale[c4+1],   s2=g_scale[c4+2],   s3=g_scale[c4+3];
    const float t0=g_shift[c4],   t1=g_shift[c4+1],   t2=g_shift[c4+2],   t3=g_shift[c4+3];
    const float u0=g_scale[128+c4],u1=g_scale[129+c4],u2=g_scale[130+c4],u3=g_scale[131+c4];
    const float w0=g_shift[128+c4],w1=g_shift[129+c4],w2=g_shift[130+c4],w3=g_shift[131+c4];
    #pragma unroll
    for (int i=0;i<8;i++){
        const int e = e0 + i;
        float4 f = *reinterpret_cast<const float4*>(Y2 + (size_t)e*256 + c4);
        float4 c = *reinterpret_cast<const float4*>(Y2 + (size_t)e*256 + 128 + c4);
        float m0 = (1.f/(1.f+__expf(-(f.x*s0+t0)))) * softplusf(c.x*u0+w0);
        float m1 = (1.f/(1.f+__expf(-(f.y*s1+t1)))) * softplusf(c.y*u1+w1);
        float m2 = (1.f/(1.f+__expf(-(f.z*s2+t2)))) * softplusf(c.z*u2+w2);
        float m3 = (1.f/(1.f+__expf(-(f.w*s3+t3)))) * softplusf(c.w*u3+w3);
        const int v = vid[e];
        red_add_v4(Hout + (size_t)v*128 + c4, m0, m1, m2, m3);
    }
}

// h += bn(Y); also emit split H
__global__ void h_update_split(float* __restrict__ H, const float* __restrict__ Y){
    const size_t i = (size_t)blockIdx.x*256 + threadIdx.x;
    const int c = (int)(i & 127);
    const float v = H[i] + Y[i]*g_scale[c] + g_shift[c];
    H[i] = v;
    __nv_bfloat16 hi, lo; split1(v, hi, lo);
    g_hhi[i] = hi; g_hlo[i] = lo;
}
__global__ void split_H(const float* __restrict__ H){
    const size_t i = (size_t)blockIdx.x*256 + threadIdx.x;
    __nv_bfloat16 hi, lo; split1(H[i], hi, lo);
    g_hhi[i] = hi; g_hlo[i] = lo;
}

// out[b] += mean_v( silu(bn(Yo)) . wo2 + bo2 )
__global__ void out_reduce(const float* __restrict__ Yo, const float* __restrict__ wo2,
                           const float* __restrict__ bo2, float* __restrict__ out)
{
    const int warp = threadIdx.x >> 5, lane = threadIdx.x & 31;
    const long n = (long)blockIdx.x*8 + warp;
    float s = 0.f;
    #pragma unroll
    for (int j=0;j<4;j++){
        const int h = lane + j*32;
        float x = Yo[(size_t)n*128 + h]*g_scale[h] + g_shift[h];
        x = siluf(x);
        s += x * wo2[h];
    }
    #pragma unroll
    for (int o=16;o>0;o>>=1) s += __shfl_xor_sync(0xFFFFFFFFu, s, o);
    if (lane == 0){
        const int b = (int)(n >> 11);
        atomicAdd(&out[b], (s + bo2[0]) * (1.f/(float)V_));
    }
}

// ---------------- launcher ----------------
extern "C" void kernel_launch(void* const* d_in, const int* in_sizes, int n_in,
                              void* d_out, int out_size)
{
    const float* chem = (const float*)d_in[0];
    const int*   vid  = (const int*  )d_in[1];
    const float* eigs = (const float*)d_in[2];
    const float* w1   = (const float*)d_in[3];
    const float* b1   = (const float*)d_in[4];
    const float* g1   = (const float*)d_in[5];
    const float* be1  = (const float*)d_in[6];
    const float* w2   = (const float*)d_in[7];
    const float* b2   = (const float*)d_in[8];
    const float* g2   = (const float*)d_in[9];
    const float* be2  = (const float*)d_in[10];
    const float* ptim = (const float*)d_in[11];
    const float* pw1  = (const float*)d_in[12];
    const float* pb1  = (const float*)d_in[13];
    const float* pg1  = (const float*)d_in[14];
    const float* pbe1 = (const float*)d_in[15];
    const float* pw2  = (const float*)d_in[16];
    const float* pb2  = (const float*)d_in[17];
    const float* pg2  = (const float*)d_in[18];
    const float* pbe2 = (const float*)d_in[19];
    const float* wo1  = (const float*)d_in[20];
    const float* bo1  = (const float*)d_in[21];
    const float* go1  = (const float*)d_in[22];
    const float* beo1 = (const float*)d_in[23];
    const float* wo2  = (const float*)d_in[24];
    const float* bo2  = (const float*)d_in[25];
    float* outp = (float*)d_out;

    void* p;
    float *pY1,*pY2,*pH,*pHS,*pYa,*pYb;
    __nv_bfloat16 *pw1hi,*pw1lo,*pw2hi,*pw2lo,*ppw1hi,*ppw1lo,*ppw2hi,*ppw2lo,*pwo1hi,*pwo1lo;
    __nv_bfloat16 *pevhi,*pevlo,*peihi,*peilo,*phshi,*phslo,*phhi,*phlo,*phphi,*phplo;
    cudaGetSymbolAddress(&p, g_Y1); pY1=(float*)p;
    cudaGetSymbolAddress(&p, g_Y2); pY2=(float*)p;
    cudaGetSymbolAddress(&p, g_H ); pH =(float*)p;
    cudaGetSymbolAddress(&p, g_HS); pHS=(float*)p;
    cudaGetSymbolAddress(&p, g_Ya); pYa=(float*)p;
    cudaGetSymbolAddress(&p, g_Yb); pYb=(float*)p;
    cudaGetSymbolAddress(&p, w1s_hi); pw1hi=(__nv_bfloat16*)p;
    cudaGetSymbolAddress(&p, w1s_lo); pw1lo=(__nv_bfloat16*)p;
    cudaGetSymbolAddress(&p, w2s_hi); pw2hi=(__nv_bfloat16*)p;
    cudaGetSymbolAddress(&p, w2s_lo); pw2lo=(__nv_bfloat16*)p;
    cudaGetSymbolAddress(&p, pw1s_hi); ppw1hi=(__nv_bfloat16*)p;
    cudaGetSymbolAddress(&p, pw1s_lo); ppw1lo=(__nv_bfloat16*)p;
    cudaGetSymbolAddress(&p, pw2s_hi); ppw2hi=(__nv_bfloat16*)p;
    cudaGetSymbolAddress(&p, pw2s_lo); ppw2lo=(__nv_bfloat16*)p;
    cudaGetSymbolAddress(&p, wo1s_hi); pwo1hi=(__nv_bfloat16*)p;
    cudaGetSymbolAddress(&p, wo1s_lo); pwo1lo=(__nv_bfloat16*)p;
    cudaGetSymbolAddress(&p, g_evhi); pevhi=(__nv_bfloat16*)p;
    cudaGetSymbolAddress(&p, g_evlo); pevlo=(__nv_bfloat16*)p;
    cudaGetSymbolAddress(&p, g_eihi); peihi=(__nv_bfloat16*)p;
    cudaGetSymbolAddress(&p, g_eilo); peilo=(__nv_bfloat16*)p;
    cudaGetSymbolAddress(&p, g_hshi); phshi=(__nv_bfloat16*)p;
    cudaGetSymbolAddress(&p, g_hslo); phslo=(__nv_bfloat16*)p;
    cudaGetSymbolAddress(&p, g_hhi ); phhi=(__nv_bfloat16*)p;
    cudaGetSymbolAddress(&p, g_hlo ); phlo=(__nv_bfloat16*)p;
    cudaGetSymbolAddress(&p, g_hphi); phphi=(__nv_bfloat16*)p;
    cudaGetSymbolAddress(&p, g_hplo); phplo=(__nv_bfloat16*)p;

    const int GSM = 2*SMBUF + 1024;     // 76800
    const int SSM = 2*SSMBUF;           // 69632
    cudaFuncSetAttribute(gemm5<0,true ,false>, cudaFuncAttributeMaxDynamicSharedMemorySize, GSM);
    cudaFuncSetAttribute(gemm5<1,true ,false>, cudaFuncAttributeMaxDynamicSharedMemorySize, GSM);
    cudaFuncSetAttribute(gemm5<3,false,true >, cudaFuncAttributeMaxDynamicSharedMemorySize, GSM);
    cudaFuncSetAttribute(gemm5<4,true ,false>, cudaFuncAttributeMaxDynamicSharedMemorySize, GSM);
    cudaFuncSetAttribute(gemm5<3,true ,false>, cudaFuncAttributeMaxDynamicSharedMemorySize, GSM);
    cudaFuncSetAttribute(spec5, cudaFuncAttributeMaxDynamicSharedMemorySize, SSM);

    zero_kernel<<<1, 64>>>(outp, 64);

    // ---- prep: pre-split static operands ----
    split_w1<<<64*128/256, 256>>>(w1);
    split_mat<<<(128*256+255)/256, 256>>>(w2, pw2hi, pw2lo, 128*256);
    split_mat<<<(3*256*128+255)/256, 256>>>(pw1, ppw1hi, ppw1lo, 3*256*128);
    split_mat<<<(3*128*128+255)/256, 256>>>(pw2, ppw2hi, ppw2lo, 3*128*128);
    split_mat<<<(128*128+255)/256, 256>>>(wo1, pwo1hi, pwo1lo, 128*128);
    split_eigs_k<<<(unsigned)(((size_t)B_*V_*K_)/256), 256>>>(eigs);

    // ---- chem MLP stage 1 ----
    zero_stats<<<1,256>>>();
    gemm5<0,true,false><<<dim3(1, E_/128, 1), 256, GSM>>>(
        chem, nullptr, nullptr, nullptr, nullptr, pw1hi, pw1lo,
        b1, pY1, nullptr, nullptr, CF_, 128, CF_, 0, 0, 0);
    finalize_bn<<<1,128>>>(g1, be1, 1.f/(float)E_);

    // ---- stage 2 ----
    zero_stats<<<1,256>>>();
    gemm5<1,true,false><<<dim3(2, E_/128, 1), 256, GSM>>>(
        pY1, nullptr, nullptr, nullptr, nullptr, pw2hi, pw2lo,
        b2, pY2, nullptr, nullptr, 128, 256, 128, 0, 0, 0);
    finalize_bn<<<1,256>>>(g2, be2, 1.f/(float)E_);

    // ---- message + segment_sum ----
    zero_kernel<<<(unsigned)(((size_t)N_*H_)/256), 256>>>(pH, (size_t)N_*H_);
    msg_scatter<<<E_/32, 128>>>(pY2, vid, pH);
    split_H<<<(unsigned)(((size_t)N_*H_)/256), 256>>>(pH);

    // ---- propagation layers ----
    for (int l = 0; l < L_; l++){
        zero_kernel<<<(B_*K_*H_+255)/256, 256>>>(pHS, (size_t)B_*K_*H_);
        spec5<<<dim3(SPLITV, 1, B_), 256, SSM>>>(pHS);
        coeff_mul_split<<<dim3(K_,B_), H_>>>(eigs, ptim, pHS, l);
        // h_prop = evecs @ (coeff*h_spec), batched over B -> split HP
        gemm5<3,false,true><<<dim3(1, V_/128, B_), 256, GSM>>>(
            nullptr, pevhi, pevlo, nullptr, nullptr, phshi, phslo,
            nullptr, nullptr, phphi, phplo, 128, 128, 128,
            (size_t)V_*K_, (size_t)K_*H_, (size_t)V_*H_);
        // z-MLP stage 1: Ya = [h, h_prop] @ pw1[l] + pb1[l]
        zero_stats<<<1,256>>>();
        gemm5<4,true,false><<<dim3(1, N_/128, 1), 256, GSM>>>(
            nullptr, phhi, phlo, phphi, phplo,
            ppw1hi + (size_t)l*256*128, ppw1lo + (size_t)l*256*128,
            pb1 + l*H_, pYa, nullptr, nullptr, 256, 128, 128, 0, 0, 0);
        finalize_bn<<<1,128>>>(pg1 + l*H_, pbe1 + l*H_, 1.f/(float)N_);
        // z-MLP stage 2: Yb = silu(bn(Ya)) @ pw2[l] + pb2[l]
        zero_stats<<<1,256>>>();
        gemm5<1,true,false><<<dim3(1, N_/128, 1), 256, GSM>>>(
            pYa, nullptr, nullptr, nullptr, nullptr,
            ppw2hi + (size_t)l*128*128, ppw2lo + (size_t)l*128*128,
            pb2 + l*H_, pYb, nullptr, nullptr, 128, 128, 128, 0, 0, 0);
        finalize_bn<<<1,128>>>(pg2 + l*H_, pbe2 + l*H_, 1.f/(float)N_);
        h_update_split<<<(unsigned)(((size_t)N_*H_)/256), 256>>>(pH, pYb);
    }

    // ---- output head ----
    zero_stats<<<1,256>>>();
    gemm5<3,true,false><<<dim3(1, N_/128, 1), 256, GSM>>>(
        nullptr, phhi, phlo, nullptr, nullptr, pwo1hi, pwo1lo,
        bo1, pYa, nullptr, nullptr, 128, 128, 128, 0, 0, 0);
    finalize_bn<<<1,128>>>(go1, beo1, 1.f/(float)N_);
    out_reduce<<<N_/8, 256>>>(pYa, wo2, bo2, outp);
}

// round 6
// speedup vs baseline: 1.9898x; 1.0083x over previous
#include <cuda_runtime.h>
#include <cuda_bf16.h>
#include <cstdint>

// ---------------- problem constants ----------------
#define B_   64
#define V_   2048
#define K_   128
#define H_   128
#define N_   (B_*V_)
#define E_   1048576
#define CF_  47
#define L_   3
#define EPSF 1e-5f

// ---------------- scratch ----------------
__device__ float g_Y1[(size_t)E_*H_];
__device__ float g_Y2[(size_t)E_*2*H_];
__device__ float g_H [(size_t)N_*H_];
__device__ float g_Ya[(size_t)N_*H_];
__device__ float g_Yb[(size_t)N_*H_];
__device__ float g_sum[256], g_sumsq[256], g_scale[256], g_shift[256];
// pre-split bf16 operands
__device__ __nv_bfloat16 w1s_hi[64*128],        w1s_lo[64*128];
__device__ __nv_bfloat16 w2s_hi[128*256],       w2s_lo[128*256];
__device__ __nv_bfloat16 pw1s_hi[3*256*128],    pw1s_lo[3*256*128];
__device__ __nv_bfloat16 pw2s_hi[3*128*128],    pw2s_lo[3*128*128];
__device__ __nv_bfloat16 wo1s_hi[128*128],      wo1s_lo[128*128];
__device__ __nv_bfloat16 g_evhi[(size_t)B_*V_*K_], g_evlo[(size_t)B_*V_*K_];
__device__ __nv_bfloat16 g_eihi[(size_t)B_*V_*K_], g_eilo[(size_t)B_*V_*K_];
__device__ __nv_bfloat16 g_hshi[(size_t)B_*K_*H_], g_hslo[(size_t)B_*K_*H_];
__device__ __nv_bfloat16 g_hhi [(size_t)N_*H_],    g_hlo [(size_t)N_*H_];
__device__ __nv_bfloat16 g_Thi [(size_t)B_*K_*H_], g_Tlo [(size_t)B_*K_*H_];

// ---------------- helpers ----------------
__device__ __forceinline__ float siluf(float x){ return x * (1.f/(1.f+__expf(-x))); }
__device__ __forceinline__ float softplusf(float x){ return x > 20.f ? x : log1pf(__expf(x)); }
__device__ __forceinline__ void red_add_v4(float* a, float x, float y, float z, float w){
    asm volatile("red.global.add.v4.f32 [%0], {%1,%2,%3,%4};"
                 :: "l"(a), "f"(x), "f"(y), "f"(z), "f"(w) : "memory");
}
__device__ __forceinline__ uint32_t smem_u32(const void* p){
    uint32_t a;
    asm("{ .reg .u64 t; cvta.to.shared.u64 t, %1; cvt.u32.u64 %0, t; }" : "=r"(a) : "l"(p));
    return a;
}
__device__ __forceinline__ void cpasync16(uint32_t s, const void* g){
    asm volatile("cp.async.ca.shared.global [%0], [%1], 16;" :: "r"(s), "l"(g));
}
#define CP_COMMIT() asm volatile("cp.async.commit_group;")
#define CP_WAIT0()  asm volatile("cp.async.wait_group 0;")

__device__ __forceinline__ void ldsm4(uint32_t* r, uint32_t addr){
    asm volatile("ldmatrix.sync.aligned.m8n8.x4.shared.b16 {%0,%1,%2,%3}, [%4];"
        : "=r"(r[0]),"=r"(r[1]),"=r"(r[2]),"=r"(r[3]) : "r"(addr));
}
__device__ __forceinline__ void ldsm4t(uint32_t* r, uint32_t addr){
    asm volatile("ldmatrix.sync.aligned.m8n8.x4.trans.shared.b16 {%0,%1,%2,%3}, [%4];"
        : "=r"(r[0]),"=r"(r[1]),"=r"(r[2]),"=r"(r[3]) : "r"(addr));
}
__device__ __forceinline__ void mma16816(float* d, const uint32_t* a, uint32_t b0, uint32_t b1){
    asm volatile("mma.sync.aligned.m16n8k16.row.col.f32.bf16.bf16.f32 "
        "{%0,%1,%2,%3}, {%4,%5,%6,%7}, {%8,%9}, {%0,%1,%2,%3};"
        : "+f"(d[0]),"+f"(d[1]),"+f"(d[2]),"+f"(d[3])
        : "r"(a[0]),"r"(a[1]),"r"(a[2]),"r"(a[3]), "r"(b0),"r"(b1));
}

__device__ __forceinline__ void split8(const float* f, uint4& hi, uint4& lo){
    unsigned h[4], l[4];
    #pragma unroll
    for (int p=0;p<4;p++){
        float2 a = make_float2(f[2*p], f[2*p+1]);
        __nv_bfloat162 bh = __float22bfloat162_rn(a);
        float hx = __bfloat162float(bh.x), hy = __bfloat162float(bh.y);
        float2 rz = make_float2(a.x - hx, a.y - hy);
        __nv_bfloat162 bl = __float22bfloat162_rn(rz);
        h[p] = *reinterpret_cast<unsigned*>(&bh);
        l[p] = *reinterpret_cast<unsigned*>(&bl);
    }
    hi = make_uint4(h[0],h[1],h[2],h[3]);
    lo = make_uint4(l[0],l[1],l[2],l[3]);
}
__device__ __forceinline__ void split1(float v, __nv_bfloat16& hi, __nv_bfloat16& lo){
    hi = __float2bfloat16_rn(v);
    lo = __float2bfloat16_rn(v - __bfloat162float(hi));
}
__device__ __forceinline__ void split2_store(__nv_bfloat16* phi, __nv_bfloat16* plo,
                                             float v0, float v1){
    __nv_bfloat162 h2 = __float22bfloat162_rn(make_float2(v0, v1));
    __nv_bfloat162 l2 = __float22bfloat162_rn(make_float2(
        v0-__bfloat162float(h2.x), v1-__bfloat162float(h2.y)));
    *reinterpret_cast<__nv_bfloat162*>(phi) = h2;
    *reinterpret_cast<__nv_bfloat162*>(plo) = l2;
}

__global__ void zero_kernel(float* __restrict__ p, size_t n){
    size_t i = (size_t)blockIdx.x*blockDim.x + threadIdx.x;
    if (i < n) p[i] = 0.f;
}
__global__ void zero_stats(){ g_sum[threadIdx.x]=0.f; g_sumsq[threadIdx.x]=0.f; }

// ---------------- prep: split kernels ----------------
__global__ void split_mat(const float* __restrict__ src, __nv_bfloat16* __restrict__ hi,
                          __nv_bfloat16* __restrict__ lo, size_t n){
    size_t i = (size_t)blockIdx.x*256 + threadIdx.x;
    if (i < n){ __nv_bfloat16 h, l; split1(src[i], h, l); hi[i]=h; lo[i]=l; }
}
__global__ void split_w1(const float* __restrict__ w1){
    int i = blockIdx.x*256 + threadIdx.x;
    int k = i >> 7, n = i & 127;
    float v = (k < CF_) ? w1[k*128 + n] : 0.f;
    __nv_bfloat16 h, l; split1(v, h, l);
    w1s_hi[i]=h; w1s_lo[i]=l;
}
__global__ void split_eigs_k(const float* __restrict__ eigs){
    size_t i = (size_t)blockIdx.x*256 + threadIdx.x;
    size_t b = i >> 18, rem = i & 0x3FFFF;
    const float* base = eigs + (b*(size_t)(2*V_+1) + 1)*K_;
    __nv_bfloat16 h, l;
    split1(base[rem], h, l);                 g_evhi[i]=h; g_evlo[i]=l;
    split1(base[(size_t)V_*K_ + rem], h, l); g_eihi[i]=h; g_eilo[i]=l;
}

// ================= pipelined HMMA split-bf16 GEMM =================
// ASRC 0: A fp32 plain, guarded scalar loads
// ASRC 1: A fp32, silu(A*scale+shift), Kd=128, lda%4==0
// ASRC 3: A pre-split bf16
// ASRC 5: dual concat: kc<4 -> (Ahi/Alo @ Bhi/Blo); kc>=4 -> (evecs[batch] @ B2[batch])
// OUTSPLIT: write Chi/Clo bf16 instead of fp32 C.
#define APITCH 80
#define BPITCH 272
#define SMBUF  37888
template<int ASRC, bool STATS, bool OUTSPLIT>
__global__ void __launch_bounds__(256,2) gemm5(
    const float* __restrict__ Af,
    const __nv_bfloat16* __restrict__ Ahi, const __nv_bfloat16* __restrict__ Alo,
    const __nv_bfloat16* __restrict__ A2hi, const __nv_bfloat16* __restrict__ A2lo,
    const __nv_bfloat16* __restrict__ Bhi, const __nv_bfloat16* __restrict__ Blo,
    const __nv_bfloat16* __restrict__ B2hi, const __nv_bfloat16* __restrict__ B2lo,
    const float* __restrict__ bias, float* __restrict__ C,
    __nv_bfloat16* __restrict__ Chi, __nv_bfloat16* __restrict__ Clo,
    int Kd, int Nd, int lda,
    size_t sAs, size_t sBs, size_t sC)
{
    extern __shared__ __align__(16) uint8_t smem[];
    const uint32_t sb = smem_u32(smem);
    const int tid = threadIdx.x;
    const int lane = tid & 31, wid = tid >> 5;
    const int warpm = wid & 3, warpn = wid >> 2;
    const int brow = blockIdx.y * 128;
    const int bcol = blockIdx.x * 128;
    const int bz   = blockIdx.z;
    Ahi += sAs*bz; Alo += sAs*bz; Bhi += sBs*bz; Blo += sBs*bz;
    if (C)   C   += sC*bz;
    if (Chi){ Chi += sC*bz; Clo += sC*bz; }
    // dual-phase bases (ASRC 5): batch derived from row block
    const int bb = brow >> 11;
    const size_t a2base = (size_t)bb*V_*K_ + (size_t)(brow & 2047)*K_;
    const size_t b2base = (size_t)bb*K_*H_;

    const int nch = (Kd + 31) >> 5;

    const int ar = tid >> 1, akh = (tid & 1) * 16;
    const int bkr = tid >> 3, bns = (tid & 7) * 16;

    auto stageB = [&](int kc, int buf){
        const __nv_bfloat16 *shi, *slo; size_t so;
        if (ASRC == 5 && kc >= 4){
            const int gk = (kc & 3)*32 + bkr;
            shi = B2hi + b2base; slo = B2lo + b2base;
            so = (size_t)gk*128 + bns;
        } else {
            const int gk = kc*32 + bkr;
            shi = Bhi; slo = Blo;
            so = (size_t)gk*Nd + bcol + bns;
        }
        const uint32_t dst = sb + buf*SMBUF + 20480 + bkr*BPITCH + bns*2;
        cpasync16(dst,             shi + so);
        cpasync16(dst + 16,        shi + so + 8);
        cpasync16(dst + 8704,      slo + so);
        cpasync16(dst + 8704 + 16, slo + so + 8);
    };
    auto stageA_async = [&](int kc, int buf){
        const __nv_bfloat16 *hi, *lo; size_t so;
        if (ASRC == 5){
            if (kc < 4){ hi = Ahi; lo = Alo; so = (size_t)(brow+ar)*128 + kc*32 + akh; }
            else { hi = A2hi + a2base; lo = A2lo + a2base;
                   so = (size_t)ar*K_ + (kc & 3)*32 + akh; }
        } else {
            hi = Ahi; lo = Alo;
            so = (size_t)(brow + ar)*lda + kc*32 + akh;
        }
        const uint32_t dst = sb + buf*SMBUF + ar*APITCH + akh*2;
        cpasync16(dst,              hi + so);
        cpasync16(dst + 16,         hi + so + 8);
        cpasync16(dst + 10240,      lo + so);
        cpasync16(dst + 10240 + 16, lo + so + 8);
    };
    auto loadA_f32 = [&](int kc, float* av){
        if (ASRC == 1){
            const float* S = Af + (size_t)(brow+ar)*lda + kc*32 + akh;
            #pragma unroll
            for (int q=0;q<4;q++) *reinterpret_cast<float4*>(&av[q*4]) =
                *reinterpret_cast<const float4*>(S + q*4);
        } else {
            #pragma unroll
            for (int j=0;j<16;j++){
                const int k = kc*32 + akh + j;
                av[j] = (k < Kd) ? Af[(size_t)(brow+ar)*lda + k] : 0.f;
            }
        }
    };
    auto storeA_f32 = [&](int kc, int buf, float* av){
        if (ASRC == 1){
            #pragma unroll
            for (int j=0;j<16;j++){
                const int k = kc*32 + akh + j;
                av[j] = siluf(av[j]*g_scale[k] + g_shift[k]);
            }
        }
        uint4 h0,l0,h1,l1;
        split8(&av[0], h0, l0);
        split8(&av[8], h1, l1);
        uint8_t* base = smem + buf*SMBUF + ar*APITCH + akh*2;
        *reinterpret_cast<uint4*>(base)              = h0;
        *reinterpret_cast<uint4*>(base + 16)         = h1;
        *reinterpret_cast<uint4*>(base + 10240)      = l0;
        *reinterpret_cast<uint4*>(base + 10240 + 16) = l1;
    };

    constexpr bool A_F32 = (ASRC == 0) || (ASRC == 1);

    float d[2][8][4];
    #pragma unroll
    for (int i=0;i<2;i++)
        #pragma unroll
        for (int j=0;j<8;j++)
            #pragma unroll
            for (int q=0;q<4;q++) d[i][j][q] = 0.f;

    float av[16];
    stageB(0, 0);
    if (A_F32){ loadA_f32(0, av); storeA_f32(0, 0, av); }
    else       stageA_async(0, 0);
    CP_COMMIT();
    CP_WAIT0();
    __syncthreads();

    for (int kc = 0; kc < nch; kc++){
        const int cur = kc & 1, nxt = cur ^ 1;
        const bool more = (kc + 1 < nch);
        if (more){
            stageB(kc+1, nxt);
            if (!A_F32) stageA_async(kc+1, nxt);
            CP_COMMIT();
            if (A_F32) loadA_f32(kc+1, av);
        }
        const uint32_t aHi = sb + cur*SMBUF;
        const uint32_t aLo = aHi + 10240;
        const uint32_t bHi = aHi + 20480;
        const uint32_t bLo = aHi + 29184;
        #pragma unroll
        for (int ks=0; ks<2; ks++){
            uint32_t ah[2][4], al[2][4];
            #pragma unroll
            for (int mb=0; mb<2; mb++){
                const uint32_t ao = (uint32_t)(warpm*32 + mb*16 + (lane & 15))*APITCH
                                  + ks*32 + ((lane >> 4)*16);
                ldsm4(ah[mb], aHi + ao);
                ldsm4(al[mb], aLo + ao);
            }
            #pragma unroll
            for (int np=0; np<4; np++){
                const int n0 = warpn*64 + np*16;
                const uint32_t bo = (uint32_t)(ks*16 + (lane & 15))*BPITCH
                                  + (uint32_t)n0*2 + ((lane >> 4)*16);
                uint32_t bh[4], bl[4];
                ldsm4t(bh, bHi + bo);
                ldsm4t(bl, bLo + bo);
                #pragma unroll
                for (int mb=0; mb<2; mb++){
                    mma16816(d[mb][np*2  ], ah[mb], bh[0], bh[1]);
                    mma16816(d[mb][np*2  ], al[mb], bh[0], bh[1]);
                    mma16816(d[mb][np*2  ], ah[mb], bl[0], bl[1]);
                    mma16816(d[mb][np*2+1], ah[mb], bh[2], bh[3]);
                    mma16816(d[mb][np*2+1], al[mb], bh[2], bh[3]);
                    mma16816(d[mb][np*2+1], ah[mb], bl[2], bl[3]);
                }
            }
        }
        if (more){
            if (A_F32) storeA_f32(kc+1, nxt, av);
            CP_WAIT0();
        }
        __syncthreads();
    }

    #pragma unroll
    for (int mb=0; mb<2; mb++){
        #pragma unroll
        for (int nb=0; nb<8; nb++){
            const int m = brow + warpm*32 + mb*16 + (lane >> 2);
            const int n = bcol + warpn*64 + nb*8 + (lane & 3)*2;
            float b0 = 0.f, b1 = 0.f;
            if (bias){ b0 = bias[n]; b1 = bias[n+1]; }
            d[mb][nb][0] += b0; d[mb][nb][1] += b1;
            d[mb][nb][2] += b0; d[mb][nb][3] += b1;
            if (OUTSPLIT){
                split2_store(Chi + (size_t)m*Nd + n, Clo + (size_t)m*Nd + n,
                             d[mb][nb][0], d[mb][nb][1]);
                split2_store(Chi + (size_t)(m+8)*Nd + n, Clo + (size_t)(m+8)*Nd + n,
                             d[mb][nb][2], d[mb][nb][3]);
            } else {
                *reinterpret_cast<float2*>(C + (size_t)m*Nd + n) =
                    make_float2(d[mb][nb][0], d[mb][nb][1]);
                *reinterpret_cast<float2*>(C + (size_t)(m+8)*Nd + n) =
                    make_float2(d[mb][nb][2], d[mb][nb][3]);
            }
        }
    }

    if (STATS){
        float* sred = reinterpret_cast<float*>(smem + 2*SMBUF);
        sred[tid] = 0.f;
        __syncthreads();
        float s[16], q[16];
        #pragma unroll
        for (int i=0;i<16;i++){ s[i]=0.f; q[i]=0.f; }
        #pragma unroll
        for (int mb=0; mb<2; mb++)
            #pragma unroll
            for (int nb=0; nb<8; nb++){
                s[nb*2+0] += d[mb][nb][0] + d[mb][nb][2];
                s[nb*2+1] += d[mb][nb][1] + d[mb][nb][3];
                q[nb*2+0] += d[mb][nb][0]*d[mb][nb][0] + d[mb][nb][2]*d[mb][nb][2];
                q[nb*2+1] += d[mb][nb][1]*d[mb][nb][1] + d[mb][nb][3]*d[mb][nb][3];
            }
        #pragma unroll
        for (int off=4; off<32; off<<=1){
            #pragma unroll
            for (int i=0;i<16;i++){
                s[i] += __shfl_xor_sync(0xFFFFFFFFu, s[i], off);
                q[i] += __shfl_xor_sync(0xFFFFFFFFu, q[i], off);
            }
        }
        if (lane < 4){
            #pragma unroll
            for (int i=0;i<16;i++){
                const int col = warpn*64 + (i>>1)*8 + (lane & 3)*2 + (i & 1);
                atomicAdd(&sred[col], s[i]);
                atomicAdd(&sred[128+col], q[i]);
            }
        }
        __syncthreads();
        if (tid < 128){
            atomicAdd(&g_sum  [bcol + tid], sred[tid]);
            atomicAdd(&g_sumsq[bcol + tid], sred[128 + tid]);
        }
    }
}

// ================= spectral forward + coeff + split (fused) =================
// one block per batch b: HS'[k,h] = exp(-eig[b,k]*t[h]) * sum_v evinv[b,v,k]*H[b,v,h]
// writes split bf16 directly (no atomics, no fp32 HS).
#define SSMBUF 34816
__global__ void __launch_bounds__(256,2) spec6(
    const float* __restrict__ eigs, const float* __restrict__ pt, int l)
{
    extern __shared__ __align__(16) uint8_t smem[];
    const uint32_t sb = smem_u32(smem);
    const int b = blockIdx.x;
    const __nv_bfloat16* Ahi = g_eihi + (size_t)b*V_*K_;
    const __nv_bfloat16* Alo = g_eilo + (size_t)b*V_*K_;
    const __nv_bfloat16* Bhi = g_hhi  + (size_t)b*V_*H_;
    const __nv_bfloat16* Blo = g_hlo  + (size_t)b*V_*H_;

    const int tid = threadIdx.x;
    const int lane = tid & 31, wid = tid >> 5;
    const int warpm = wid & 3, warpn = wid >> 2;
    const int vr = tid >> 3, cs = (tid & 7) * 16;
    const int nch = V_/32;   // 64

    auto stage = [&](int vc, int buf){
        const int v = vc*32 + vr;
        const size_t soA = (size_t)v*K_ + cs;
        const size_t soB = (size_t)v*H_ + cs;
        const uint32_t base = sb + buf*SSMBUF + vr*BPITCH + cs*2;
        cpasync16(base,              Ahi + soA);
        cpasync16(base + 16,         Ahi + soA + 8);
        cpasync16(base + 8704,       Alo + soA);
        cpasync16(base + 8704 + 16,  Alo + soA + 8);
        cpasync16(base + 17408,      Bhi + soB);
        cpasync16(base + 17408 + 16, Bhi + soB + 8);
        cpasync16(base + 26112,      Blo + soB);
        cpasync16(base + 26112 + 16, Blo + soB + 8);
    };

    float d[2][8][4];
    #pragma unroll
    for (int i=0;i<2;i++)
        #pragma unroll
        for (int j=0;j<8;j++)
            #pragma unroll
            for (int q=0;q<4;q++) d[i][j][q] = 0.f;

    stage(0, 0);
    CP_COMMIT();
    CP_WAIT0();
    __syncthreads();

    for (int vc = 0; vc < nch; vc++){
        const int cur = vc & 1, nxt = cur ^ 1;
        const bool more = (vc + 1 < nch);
        if (more){ stage(vc+1, nxt); CP_COMMIT(); }

        const uint32_t aHi = sb + cur*SSMBUF;
        const uint32_t aLo = aHi + 8704;
        const uint32_t bHi = aHi + 17408;
        const uint32_t bLo = aHi + 26112;
        #pragma unroll
        for (int ks=0; ks<2; ks++){
            uint32_t ah[2][4], al[2][4];
            #pragma unroll
            for (int mb=0; mb<2; mb++){
                const uint32_t ao = (uint32_t)(ks*16 + (lane & 7) + ((lane >> 4)*8))*BPITCH
                                  + (uint32_t)(warpm*32 + mb*16)*2 + (((lane >> 3) & 1)*16);
                ldsm4t(ah[mb], aHi + ao);
                ldsm4t(al[mb], aLo + ao);
            }
            #pragma unroll
            for (int np=0; np<4; np++){
                const int n0 = warpn*64 + np*16;
                const uint32_t bo = (uint32_t)(ks*16 + (lane & 15))*BPITCH
                                  + (uint32_t)n0*2 + ((lane >> 4)*16);
                uint32_t bh[4], bl[4];
                ldsm4t(bh, bHi + bo);
                ldsm4t(bl, bLo + bo);
                #pragma unroll
                for (int mb=0; mb<2; mb++){
                    mma16816(d[mb][np*2  ], ah[mb], bh[0], bh[1]);
                    mma16816(d[mb][np*2  ], al[mb], bh[0], bh[1]);
                    mma16816(d[mb][np*2  ], ah[mb], bl[0], bl[1]);
                    mma16816(d[mb][np*2+1], ah[mb], bh[2], bh[3]);
                    mma16816(d[mb][np*2+1], al[mb], bh[2], bh[3]);
                    mma16816(d[mb][np*2+1], ah[mb], bl[2], bl[3]);
                }
            }
        }
        if (more) CP_WAIT0();
        __syncthreads();
    }

    // ---- fused coeff * HS, split store ----
    const float* evrow = eigs + (size_t)b*(2*V_+1)*K_;
    __nv_bfloat16* HShi = g_hshi + (size_t)b*K_*H_;
    __nv_bfloat16* HSlo = g_hslo + (size_t)b*K_*H_;
    #pragma unroll
    for (int mb=0; mb<2; mb++){
        const int m = warpm*32 + mb*16 + (lane >> 2);
        const float e0 = evrow[m], e1 = evrow[m+8];
        #pragma unroll
        for (int nb=0; nb<8; nb++){
            const int n = warpn*64 + nb*8 + (lane & 3)*2;
            const float t0 = fmaxf(pt[l*H_ + n],     1e-6f);
            const float t1 = fmaxf(pt[l*H_ + n + 1], 1e-6f);
            split2_store(HShi + (size_t)m*H_ + n, HSlo + (size_t)m*H_ + n,
                         d[mb][nb][0]*__expf(-e0*t0), d[mb][nb][1]*__expf(-e0*t1));
            split2_store(HShi + (size_t)(m+8)*H_ + n, HSlo + (size_t)(m+8)*H_ + n,
                         d[mb][nb][2]*__expf(-e1*t0), d[mb][nb][3]*__expf(-e1*t1));
        }
    }
}

__global__ void finalize_bn(const float* __restrict__ g, const float* __restrict__ be, float Rinv){
    const int c = threadIdx.x;
    const float m   = g_sum[c]*Rinv;
    const float var = g_sumsq[c]*Rinv - m*m;
    const float sc  = g[c] * rsqrtf(var + EPSF);
    g_scale[c] = sc;
    g_shift[c] = be[c] - m*sc;
}

// ---------------- message + scatter-add ----------------
__global__ void msg_scatter(const float* __restrict__ Y2, const int* __restrict__ vid,
                            float* __restrict__ Hout)
{
    const int sub = threadIdx.x >> 5;
    const int c4  = (threadIdx.x & 31) * 4;
    const int e0  = blockIdx.x * 32 + sub * 8;
    const float s0=g_scale[c4],   s1=g_scale[c4+1],   s2=g_scale[c4+2],   s3=g_scale[c4+3];
    const float t0=g_shift[c4],   t1=g_shift[c4+1],   t2=g_shift[c4+2],   t3=g_shift[c4+3];
    const float u0=g_scale[128+c4],u1=g_scale[129+c4],u2=g_scale[130+c4],u3=g_scale[131+c4];
    const float w0=g_shift[128+c4],w1=g_shift[129+c4],w2=g_shift[130+c4],w3=g_shift[131+c4];
    #pragma unroll
    for (int i=0;i<8;i++){
        const int e = e0 + i;
        float4 f = *reinterpret_cast<const float4*>(Y2 + (size_t)e*256 + c4);
        float4 c = *reinterpret_cast<const float4*>(Y2 + (size_t)e*256 + 128 + c4);
        float m0 = (1.f/(1.f+__expf(-(f.x*s0+t0)))) * softplusf(c.x*u0+w0);
        float m1 = (1.f/(1.f+__expf(-(f.y*s1+t1)))) * softplusf(c.y*u1+w1);
        float m2 = (1.f/(1.f+__expf(-(f.z*s2+t2)))) * softplusf(c.z*u2+w2);
        float m3 = (1.f/(1.f+__expf(-(f.w*s3+t3)))) * softplusf(c.w*u3+w3);
        const int v = vid[e];
        red_add_v4(Hout + (size_t)v*128 + c4, m0, m1, m2, m3);
    }
}

// h += bn(Y); also emit split H
__global__ void h_update_split(float* __restrict__ H, const float* __restrict__ Y){
    const size_t i = (size_t)blockIdx.x*256 + threadIdx.x;
    const int c = (int)(i & 127);
    const float v = H[i] + Y[i]*g_scale[c] + g_shift[c];
    H[i] = v;
    __nv_bfloat16 hi, lo; split1(v, hi, lo);
    g_hhi[i] = hi; g_hlo[i] = lo;
}
__global__ void split_H(const float* __restrict__ H){
    const size_t i = (size_t)blockIdx.x*256 + threadIdx.x;
    __nv_bfloat16 hi, lo; split1(H[i], hi, lo);
    g_hhi[i] = hi; g_hlo[i] = lo;
}

// out[b] += mean_v( silu(bn(Yo)) . wo2 + bo2 )
__global__ void out_reduce(const float* __restrict__ Yo, const float* __restrict__ wo2,
                           const float* __restrict__ bo2, float* __restrict__ out)
{
    const int warp = threadIdx.x >> 5, lane = threadIdx.x & 31;
    const long n = (long)blockIdx.x*8 + warp;
    float s = 0.f;
    #pragma unroll
    for (int j=0;j<4;j++){
        const int h = lane + j*32;
        float x = Yo[(size_t)n*128 + h]*g_scale[h] + g_shift[h];
        x = siluf(x);
        s += x * wo2[h];
    }
    #pragma unroll
    for (int o=16;o>0;o>>=1) s += __shfl_xor_sync(0xFFFFFFFFu, s, o);
    if (lane == 0){
        const int b = (int)(n >> 11);
        atomicAdd(&out[b], (s + bo2[0]) * (1.f/(float)V_));
    }
}

// ---------------- launcher ----------------
extern "C" void kernel_launch(void* const* d_in, const int* in_sizes, int n_in,
                              void* d_out, int out_size)
{
    const float* chem = (const float*)d_in[0];
    const int*   vid  = (const int*  )d_in[1];
    const float* eigs = (const float*)d_in[2];
    const float* w1   = (const float*)d_in[3];
    const float* b1   = (const float*)d_in[4];
    const float* g1   = (const float*)d_in[5];
    const float* be1  = (const float*)d_in[6];
    const float* w2   = (const float*)d_in[7];
    const float* b2   = (const float*)d_in[8];
    const float* g2   = (const float*)d_in[9];
    const float* be2  = (const float*)d_in[10];
    const float* ptim = (const float*)d_in[11];
    const float* pw1  = (const float*)d_in[12];
    const float* pb1  = (const float*)d_in[13];
    const float* pg1  = (const float*)d_in[14];
    const float* pbe1 = (const float*)d_in[15];
    const float* pw2  = (const float*)d_in[16];
    const float* pb2  = (const float*)d_in[17];
    const float* pg2  = (const float*)d_in[18];
    const float* pbe2 = (const float*)d_in[19];
    const float* wo1  = (const float*)d_in[20];
    const float* bo1  = (const float*)d_in[21];
    const float* go1  = (const float*)d_in[22];
    const float* beo1 = (const float*)d_in[23];
    const float* wo2  = (const float*)d_in[24];
    const float* bo2  = (const float*)d_in[25];
    float* outp = (float*)d_out;

    void* p;
    float *pY1,*pY2,*pH,*pYa,*pYb;
    __nv_bfloat16 *pw1hi,*pw1lo,*pw2hi,*pw2lo,*ppw1hi,*ppw1lo,*ppw2hi,*ppw2lo,*pwo1hi,*pwo1lo;
    __nv_bfloat16 *pevhi,*pevlo,*phshi,*phslo,*phhi,*phlo,*pThi,*pTlo;
    cudaGetSymbolAddress(&p, g_Y1); pY1=(float*)p;
    cudaGetSymbolAddress(&p, g_Y2); pY2=(float*)p;
    cudaGetSymbolAddress(&p, g_H ); pH =(float*)p;
    cudaGetSymbolAddress(&p, g_Ya); pYa=(float*)p;
    cudaGetSymbolAddress(&p, g_Yb); pYb=(float*)p;
    cudaGetSymbolAddress(&p, w1s_hi); pw1hi=(__nv_bfloat16*)p;
    cudaGetSymbolAddress(&p, w1s_lo); pw1lo=(__nv_bfloat16*)p;
    cudaGetSymbolAddress(&p, w2s_hi); pw2hi=(__nv_bfloat16*)p;
    cudaGetSymbolAddress(&p, w2s_lo); pw2lo=(__nv_bfloat16*)p;
    cudaGetSymbolAddress(&p, pw1s_hi); ppw1hi=(__nv_bfloat16*)p;
    cudaGetSymbolAddress(&p, pw1s_lo); ppw1lo=(__nv_bfloat16*)p;
    cudaGetSymbolAddress(&p, pw2s_hi); ppw2hi=(__nv_bfloat16*)p;
    cudaGetSymbolAddress(&p, pw2s_lo); ppw2lo=(__nv_bfloat16*)p;
    cudaGetSymbolAddress(&p, wo1s_hi); pwo1hi=(__nv_bfloat16*)p;
    cudaGetSymbolAddress(&p, wo1s_lo); pwo1lo=(__nv_bfloat16*)p;
    cudaGetSymbolAddress(&p, g_evhi); pevhi=(__nv_bfloat16*)p;
    cudaGetSymbolAddress(&p, g_evlo); pevlo=(__nv_bfloat16*)p;
    cudaGetSymbolAddress(&p, g_hshi); phshi=(__nv_bfloat16*)p;
    cudaGetSymbolAddress(&p, g_hslo); phslo=(__nv_bfloat16*)p;
    cudaGetSymbolAddress(&p, g_hhi ); phhi=(__nv_bfloat16*)p;
    cudaGetSymbolAddress(&p, g_hlo ); phlo=(__nv_bfloat16*)p;
    cudaGetSymbolAddress(&p, g_Thi ); pThi=(__nv_bfloat16*)p;
    cudaGetSymbolAddress(&p, g_Tlo ); pTlo=(__nv_bfloat16*)p;

    const int GSM = 2*SMBUF + 1024;
    const int SSM = 2*SSMBUF;
    cudaFuncSetAttribute(gemm5<0,true ,false>, cudaFuncAttributeMaxDynamicSharedMemorySize, GSM);
    cudaFuncSetAttribute(gemm5<1,true ,false>, cudaFuncAttributeMaxDynamicSharedMemorySize, GSM);
    cudaFuncSetAttribute(gemm5<3,false,true >, cudaFuncAttributeMaxDynamicSharedMemorySize, GSM);
    cudaFuncSetAttribute(gemm5<5,true ,false>, cudaFuncAttributeMaxDynamicSharedMemorySize, GSM);
    cudaFuncSetAttribute(gemm5<3,true ,false>, cudaFuncAttributeMaxDynamicSharedMemorySize, GSM);
    cudaFuncSetAttribute(spec6, cudaFuncAttributeMaxDynamicSharedMemorySize, SSM);

    zero_kernel<<<1, 64>>>(outp, 64);

    // ---- prep ----
    split_w1<<<64*128/256, 256>>>(w1);
    split_mat<<<(128*256+255)/256, 256>>>(w2, pw2hi, pw2lo, 128*256);
    split_mat<<<(3*256*128+255)/256, 256>>>(pw1, ppw1hi, ppw1lo, 3*256*128);
    split_mat<<<(3*128*128+255)/256, 256>>>(pw2, ppw2hi, ppw2lo, 3*128*128);
    split_mat<<<(128*128+255)/256, 256>>>(wo1, pwo1hi, pwo1lo, 128*128);
    split_eigs_k<<<(unsigned)(((size_t)B_*V_*K_)/256), 256>>>(eigs);

    // ---- chem MLP stage 1 ----
    zero_stats<<<1,256>>>();
    gemm5<0,true,false><<<dim3(1, E_/128, 1), 256, GSM>>>(
        chem, nullptr, nullptr, nullptr, nullptr, pw1hi, pw1lo, nullptr, nullptr,
        b1, pY1, nullptr, nullptr, CF_, 128, CF_, 0, 0, 0);
    finalize_bn<<<1,128>>>(g1, be1, 1.f/(float)E_);

    // ---- stage 2 ----
    zero_stats<<<1,256>>>();
    gemm5<1,true,false><<<dim3(2, E_/128, 1), 256, GSM>>>(
        pY1, nullptr, nullptr, nullptr, nullptr, pw2hi, pw2lo, nullptr, nullptr,
        b2, pY2, nullptr, nullptr, 128, 256, 128, 0, 0, 0);
    finalize_bn<<<1,256>>>(g2, be2, 1.f/(float)E_);

    // ---- message + segment_sum ----
    zero_kernel<<<(unsigned)(((size_t)N_*H_)/256), 256>>>(pH, (size_t)N_*H_);
    msg_scatter<<<E_/32, 128>>>(pY2, vid, pH);
    split_H<<<(unsigned)(((size_t)N_*H_)/256), 256>>>(pH);

    // ---- propagation layers ----
    for (int l = 0; l < L_; l++){
        // HS' = coeff .* (evinv^T @ h)   (fused, split output)
        spec6<<<B_, 256, SSM>>>(eigs, ptim, l);
        // T[b] = HS'[b] @ W1b  (tiny batched GEMM, split output)
        gemm5<3,false,true><<<dim3(1, 1, B_), 256, GSM>>>(
            nullptr, phshi, phslo, nullptr, nullptr,
            ppw1hi + (size_t)l*256*128 + 128*128, ppw1lo + (size_t)l*256*128 + 128*128,
            nullptr, nullptr, nullptr, nullptr, pThi, pTlo,
            128, 128, 128, (size_t)K_*H_, 0, (size_t)K_*H_);
        // zMLP1: Ya = h @ W1a + evecs @ T[b] + pb1[l]   (dual concat, stats fused)
        zero_stats<<<1,256>>>();
        gemm5<5,true,false><<<dim3(1, N_/128, 1), 256, GSM>>>(
            nullptr, phhi, phlo, pevhi, pevlo,
            ppw1hi + (size_t)l*256*128, ppw1lo + (size_t)l*256*128, pThi, pTlo,
            pb1 + l*H_, pYa, nullptr, nullptr, 256, 128, 128, 0, 0, 0);
        finalize_bn<<<1,128>>>(pg1 + l*H_, pbe1 + l*H_, 1.f/(float)N_);
        // zMLP2: Yb = silu(bn(Ya)) @ pw2[l] + pb2[l]
        zero_stats<<<1,256>>>();
        gemm5<1,true,false><<<dim3(1, N_/128, 1), 256, GSM>>>(
            pYa, nullptr, nullptr, nullptr, nullptr,
            ppw2hi + (size_t)l*128*128, ppw2lo + (size_t)l*128*128, nullptr, nullptr,
            pb2 + l*H_, pYb, nullptr, nullptr, 128, 128, 128, 0, 0, 0);
        finalize_bn<<<1,128>>>(pg2 + l*H_, pbe2 + l*H_, 1.f/(float)N_);
        h_update_split<<<(unsigned)(((size_t)N_*H_)/256), 256>>>(pH, pYb);
    }

    // ---- output head ----
    zero_stats<<<1,256>>>();
    gemm5<3,true,false><<<dim3(1, N_/128, 1), 256, GSM>>>(
        nullptr, phhi, phlo, nullptr, nullptr, pwo1hi, pwo1lo, nullptr, nullptr,
        bo1, pYa, nullptr, nullptr, 128, 128, 128, 0, 0, 0);
    finalize_bn<<<1,128>>>(go1, beo1, 1.f/(float)N_);
    out_reduce<<<N_/8, 256>>>(pYa, wo2, bo2, outp);
}

// round 7
// speedup vs baseline: 2.0646x; 1.0376x over previous
#include <cuda_runtime.h>
#include <cuda_bf16.h>
#include <cstdint>

// ---------------- problem constants ----------------
#define B_   64
#define V_   2048
#define K_   128
#define H_   128
#define N_   (B_*V_)
#define E_   1048576
#define CF_  47
#define L_   3
#define EPSF 1e-5f
#define SPLITV 4

// ---------------- scratch ----------------
__device__ float g_Y1[(size_t)E_*H_];
__device__ float g_Y2[(size_t)E_*2*H_];
__device__ float g_H [(size_t)N_*H_];
__device__ float g_HS[(size_t)B_*K_*H_];
__device__ float g_Ya[(size_t)N_*H_];
__device__ float g_Yb[(size_t)N_*H_];
__device__ float g_sum[256], g_sumsq[256], g_scale[256], g_shift[256];
// pre-split bf16 operands
__device__ __nv_bfloat16 w1s_hi[64*128],        w1s_lo[64*128];
__device__ __nv_bfloat16 w2s_hi[128*256],       w2s_lo[128*256];
__device__ __nv_bfloat16 pw1s_hi[3*256*128],    pw1s_lo[3*256*128];
__device__ __nv_bfloat16 pw2s_hi[3*128*128],    pw2s_lo[3*128*128];
__device__ __nv_bfloat16 wo1s_hi[128*128],      wo1s_lo[128*128];
__device__ __nv_bfloat16 g_evhi[(size_t)B_*V_*K_], g_evlo[(size_t)B_*V_*K_];
__device__ __nv_bfloat16 g_eihi[(size_t)B_*V_*K_], g_eilo[(size_t)B_*V_*K_];
__device__ __nv_bfloat16 g_hshi[(size_t)B_*K_*H_], g_hslo[(size_t)B_*K_*H_];
__device__ __nv_bfloat16 g_hhi [(size_t)N_*H_],    g_hlo [(size_t)N_*H_];
__device__ __nv_bfloat16 g_Thi [(size_t)B_*K_*H_], g_Tlo [(size_t)B_*K_*H_];

// ---------------- helpers ----------------
__device__ __forceinline__ float siluf(float x){ return x * (1.f/(1.f+__expf(-x))); }
__device__ __forceinline__ float softplusf(float x){ return x > 20.f ? x : log1pf(__expf(x)); }
__device__ __forceinline__ void red_add_v4(float* a, float x, float y, float z, float w){
    asm volatile("red.global.add.v4.f32 [%0], {%1,%2,%3,%4};"
                 :: "l"(a), "f"(x), "f"(y), "f"(z), "f"(w) : "memory");
}
__device__ __forceinline__ void red_add_v2(float* a, float x, float y){
    asm volatile("red.global.add.v2.f32 [%0], {%1,%2};" :: "l"(a), "f"(x), "f"(y) : "memory");
}
__device__ __forceinline__ uint32_t smem_u32(const void* p){
    uint32_t a;
    asm("{ .reg .u64 t; cvta.to.shared.u64 t, %1; cvt.u32.u64 %0, t; }" : "=r"(a) : "l"(p));
    return a;
}
__device__ __forceinline__ void cpasync16(uint32_t s, const void* g){
    asm volatile("cp.async.ca.shared.global [%0], [%1], 16;" :: "r"(s), "l"(g));
}
#define CP_COMMIT() asm volatile("cp.async.commit_group;")
#define CP_WAIT0()  asm volatile("cp.async.wait_group 0;")

__device__ __forceinline__ void ldsm4(uint32_t* r, uint32_t addr){
    asm volatile("ldmatrix.sync.aligned.m8n8.x4.shared.b16 {%0,%1,%2,%3}, [%4];"
        : "=r"(r[0]),"=r"(r[1]),"=r"(r[2]),"=r"(r[3]) : "r"(addr));
}
__device__ __forceinline__ void ldsm4t(uint32_t* r, uint32_t addr){
    asm volatile("ldmatrix.sync.aligned.m8n8.x4.trans.shared.b16 {%0,%1,%2,%3}, [%4];"
        : "=r"(r[0]),"=r"(r[1]),"=r"(r[2]),"=r"(r[3]) : "r"(addr));
}
__device__ __forceinline__ void mma16816(float* d, const uint32_t* a, uint32_t b0, uint32_t b1){
    asm volatile("mma.sync.aligned.m16n8k16.row.col.f32.bf16.bf16.f32 "
        "{%0,%1,%2,%3}, {%4,%5,%6,%7}, {%8,%9}, {%0,%1,%2,%3};"
        : "+f"(d[0]),"+f"(d[1]),"+f"(d[2]),"+f"(d[3])
        : "r"(a[0]),"r"(a[1]),"r"(a[2]),"r"(a[3]), "r"(b0),"r"(b1));
}

__device__ __forceinline__ void split8(const float* f, uint4& hi, uint4& lo){
    unsigned h[4], l[4];
    #pragma unroll
    for (int p=0;p<4;p++){
        float2 a = make_float2(f[2*p], f[2*p+1]);
        __nv_bfloat162 bh = __float22bfloat162_rn(a);
        float hx = __bfloat162float(bh.x), hy = __bfloat162float(bh.y);
        float2 rz = make_float2(a.x - hx, a.y - hy);
        __nv_bfloat162 bl = __float22bfloat162_rn(rz);
        h[p] = *reinterpret_cast<unsigned*>(&bh);
        l[p] = *reinterpret_cast<unsigned*>(&bl);
    }
    hi = make_uint4(h[0],h[1],h[2],h[3]);
    lo = make_uint4(l[0],l[1],l[2],l[3]);
}
__device__ __forceinline__ void split1(float v, __nv_bfloat16& hi, __nv_bfloat16& lo){
    hi = __float2bfloat16_rn(v);
    lo = __float2bfloat16_rn(v - __bfloat162float(hi));
}
__device__ __forceinline__ void split2_store(__nv_bfloat16* phi, __nv_bfloat16* plo,
                                             float v0, float v1){
    __nv_bfloat162 h2 = __float22bfloat162_rn(make_float2(v0, v1));
    __nv_bfloat162 l2 = __float22bfloat162_rn(make_float2(
        v0-__bfloat162float(h2.x), v1-__bfloat162float(h2.y)));
    *reinterpret_cast<__nv_bfloat162*>(phi) = h2;
    *reinterpret_cast<__nv_bfloat162*>(plo) = l2;
}

__global__ void zero_kernel(float* __restrict__ p, size_t n){
    size_t i = (size_t)blockIdx.x*blockDim.x + threadIdx.x;
    if (i < n) p[i] = 0.f;
}
__global__ void zero_stats(){ g_sum[threadIdx.x]=0.f; g_sumsq[threadIdx.x]=0.f; }

// ---------------- prep: split kernels ----------------
__global__ void split_mat(const float* __restrict__ src, __nv_bfloat16* __restrict__ hi,
                          __nv_bfloat16* __restrict__ lo, size_t n){
    size_t i = (size_t)blockIdx.x*256 + threadIdx.x;
    if (i < n){ __nv_bfloat16 h, l; split1(src[i], h, l); hi[i]=h; lo[i]=l; }
}
__global__ void split_w1(const float* __restrict__ w1){
    int i = blockIdx.x*256 + threadIdx.x;
    int k = i >> 7, n = i & 127;
    float v = (k < CF_) ? w1[k*128 + n] : 0.f;
    __nv_bfloat16 h, l; split1(v, h, l);
    w1s_hi[i]=h; w1s_lo[i]=l;
}
__global__ void split_eigs_k(const float* __restrict__ eigs){
    size_t i = (size_t)blockIdx.x*256 + threadIdx.x;
    size_t b = i >> 18, rem = i & 0x3FFFF;
    const float* base = eigs + (b*(size_t)(2*V_+1) + 1)*K_;
    __nv_bfloat16 h, l;
    split1(base[rem], h, l);                 g_evhi[i]=h; g_evlo[i]=l;
    split1(base[(size_t)V_*K_ + rem], h, l); g_eihi[i]=h; g_eilo[i]=l;
}

// ================= pipelined HMMA split-bf16 GEMM =================
// ASRC 0: A fp32 plain, guarded scalar loads
// ASRC 1: A fp32, silu(A*scale+shift), Kd=128, lda%4==0
// ASRC 3: A pre-split bf16
// ASRC 5: dual concat: kc<4 -> (Ahi/Alo @ Bhi/Blo); kc>=4 -> (evecs[batch] @ B2[batch])
#define APITCH 80
#define BPITCH 272
#define SMBUF  37888
template<int ASRC, bool STATS, bool OUTSPLIT>
__global__ void __launch_bounds__(256,2) gemm5(
    const float* __restrict__ Af,
    const __nv_bfloat16* __restrict__ Ahi, const __nv_bfloat16* __restrict__ Alo,
    const __nv_bfloat16* __restrict__ A2hi, const __nv_bfloat16* __restrict__ A2lo,
    const __nv_bfloat16* __restrict__ Bhi, const __nv_bfloat16* __restrict__ Blo,
    const __nv_bfloat16* __restrict__ B2hi, const __nv_bfloat16* __restrict__ B2lo,
    const float* __restrict__ bias, float* __restrict__ C,
    __nv_bfloat16* __restrict__ Chi, __nv_bfloat16* __restrict__ Clo,
    int Kd, int Nd, int lda,
    size_t sAs, size_t sBs, size_t sC)
{
    extern __shared__ __align__(16) uint8_t smem[];
    const uint32_t sb = smem_u32(smem);
    const int tid = threadIdx.x;
    const int lane = tid & 31, wid = tid >> 5;
    const int warpm = wid & 3, warpn = wid >> 2;
    const int brow = blockIdx.y * 128;
    const int bcol = blockIdx.x * 128;
    const int bz   = blockIdx.z;
    Ahi += sAs*bz; Alo += sAs*bz; Bhi += sBs*bz; Blo += sBs*bz;
    if (C)   C   += sC*bz;
    if (Chi){ Chi += sC*bz; Clo += sC*bz; }
    const int bb = brow >> 11;
    const size_t a2base = (size_t)bb*V_*K_ + (size_t)(brow & 2047)*K_;
    const size_t b2base = (size_t)bb*K_*H_;

    const int nch = (Kd + 31) >> 5;

    const int ar = tid >> 1, akh = (tid & 1) * 16;
    const int bkr = tid >> 3, bns = (tid & 7) * 16;

    auto stageB = [&](int kc, int buf){
        const __nv_bfloat16 *shi, *slo; size_t so;
        if (ASRC == 5 && kc >= 4){
            const int gk = (kc & 3)*32 + bkr;
            shi = B2hi + b2base; slo = B2lo + b2base;
            so = (size_t)gk*128 + bns;
        } else {
            const int gk = kc*32 + bkr;
            shi = Bhi; slo = Blo;
            so = (size_t)gk*Nd + bcol + bns;
        }
        const uint32_t dst = sb + buf*SMBUF + 20480 + bkr*BPITCH + bns*2;
        cpasync16(dst,             shi + so);
        cpasync16(dst + 16,        shi + so + 8);
        cpasync16(dst + 8704,      slo + so);
        cpasync16(dst + 8704 + 16, slo + so + 8);
    };
    auto stageA_async = [&](int kc, int buf){
        const __nv_bfloat16 *hi, *lo; size_t so;
        if (ASRC == 5){
            if (kc < 4){ hi = Ahi; lo = Alo; so = (size_t)(brow+ar)*128 + kc*32 + akh; }
            else { hi = A2hi + a2base; lo = A2lo + a2base;
                   so = (size_t)ar*K_ + (kc & 3)*32 + akh; }
        } else {
            hi = Ahi; lo = Alo;
            so = (size_t)(brow + ar)*lda + kc*32 + akh;
        }
        const uint32_t dst = sb + buf*SMBUF + ar*APITCH + akh*2;
        cpasync16(dst,              hi + so);
        cpasync16(dst + 16,         hi + so + 8);
        cpasync16(dst + 10240,      lo + so);
        cpasync16(dst + 10240 + 16, lo + so + 8);
    };
    auto loadA_f32 = [&](int kc, float* av){
        if (ASRC == 1){
            const float* S = Af + (size_t)(brow+ar)*lda + kc*32 + akh;
            #pragma unroll
            for (int q=0;q<4;q++) *reinterpret_cast<float4*>(&av[q*4]) =
                *reinterpret_cast<const float4*>(S + q*4);
        } else {
            #pragma unroll
            for (int j=0;j<16;j++){
                const int k = kc*32 + akh + j;
                av[j] = (k < Kd) ? Af[(size_t)(brow+ar)*lda + k] : 0.f;
            }
        }
    };
    auto storeA_f32 = [&](int kc, int buf, float* av){
        if (ASRC == 1){
            #pragma unroll
            for (int j=0;j<16;j++){
                const int k = kc*32 + akh + j;
                av[j] = siluf(av[j]*g_scale[k] + g_shift[k]);
            }
        }
        uint4 h0,l0,h1,l1;
        split8(&av[0], h0, l0);
        split8(&av[8], h1, l1);
        uint8_t* base = smem + buf*SMBUF + ar*APITCH + akh*2;
        *reinterpret_cast<uint4*>(base)              = h0;
        *reinterpret_cast<uint4*>(base + 16)         = h1;
        *reinterpret_cast<uint4*>(base + 10240)      = l0;
        *reinterpret_cast<uint4*>(base + 10240 + 16) = l1;
    };

    constexpr bool A_F32 = (ASRC == 0) || (ASRC == 1);

    float d[2][8][4];
    #pragma unroll
    for (int i=0;i<2;i++)
        #pragma unroll
        for (int j=0;j<8;j++)
            #pragma unroll
            for (int q=0;q<4;q++) d[i][j][q] = 0.f;

    float av[16];
    stageB(0, 0);
    if (A_F32){ loadA_f32(0, av); storeA_f32(0, 0, av); }
    else       stageA_async(0, 0);
    CP_COMMIT();
    CP_WAIT0();
    __syncthreads();

    for (int kc = 0; kc < nch; kc++){
        const int cur = kc & 1, nxt = cur ^ 1;
        const bool more = (kc + 1 < nch);
        if (more){
            stageB(kc+1, nxt);
            if (!A_F32) stageA_async(kc+1, nxt);
            CP_COMMIT();
            if (A_F32) loadA_f32(kc+1, av);
        }
        const uint32_t aHi = sb + cur*SMBUF;
        const uint32_t aLo = aHi + 10240;
        const uint32_t bHi = aHi + 20480;
        const uint32_t bLo = aHi + 29184;
        #pragma unroll
        for (int ks=0; ks<2; ks++){
            uint32_t ah[2][4], al[2][4];
            #pragma unroll
            for (int mb=0; mb<2; mb++){
                const uint32_t ao = (uint32_t)(warpm*32 + mb*16 + (lane & 15))*APITCH
                                  + ks*32 + ((lane >> 4)*16);
                ldsm4(ah[mb], aHi + ao);
                ldsm4(al[mb], aLo + ao);
            }
            #pragma unroll
            for (int np=0; np<4; np++){
                const int n0 = warpn*64 + np*16;
                const uint32_t bo = (uint32_t)(ks*16 + (lane & 15))*BPITCH
                                  + (uint32_t)n0*2 + ((lane >> 4)*16);
                uint32_t bh[4], bl[4];
                ldsm4t(bh, bHi + bo);
                ldsm4t(bl, bLo + bo);
                #pragma unroll
                for (int mb=0; mb<2; mb++){
                    mma16816(d[mb][np*2  ], ah[mb], bh[0], bh[1]);
                    mma16816(d[mb][np*2  ], al[mb], bh[0], bh[1]);
                    mma16816(d[mb][np*2  ], ah[mb], bl[0], bl[1]);
                    mma16816(d[mb][np*2+1], ah[mb], bh[2], bh[3]);
                    mma16816(d[mb][np*2+1], al[mb], bh[2], bh[3]);
                    mma16816(d[mb][np*2+1], ah[mb], bl[2], bl[3]);
                }
            }
        }
        if (more){
            if (A_F32) storeA_f32(kc+1, nxt, av);
            CP_WAIT0();
        }
        __syncthreads();
    }

    #pragma unroll
    for (int mb=0; mb<2; mb++){
        #pragma unroll
        for (int nb=0; nb<8; nb++){
            const int m = brow + warpm*32 + mb*16 + (lane >> 2);
            const int n = bcol + warpn*64 + nb*8 + (lane & 3)*2;
            float b0 = 0.f, b1 = 0.f;
            if (bias){ b0 = bias[n]; b1 = bias[n+1]; }
            d[mb][nb][0] += b0; d[mb][nb][1] += b1;
            d[mb][nb][2] += b0; d[mb][nb][3] += b1;
            if (OUTSPLIT){
                split2_store(Chi + (size_t)m*Nd + n, Clo + (size_t)m*Nd + n,
                             d[mb][nb][0], d[mb][nb][1]);
                split2_store(Chi + (size_t)(m+8)*Nd + n, Clo + (size_t)(m+8)*Nd + n,
                             d[mb][nb][2], d[mb][nb][3]);
            } else {
                *reinterpret_cast<float2*>(C + (size_t)m*Nd + n) =
                    make_float2(d[mb][nb][0], d[mb][nb][1]);
                *reinterpret_cast<float2*>(C + (size_t)(m+8)*Nd + n) =
                    make_float2(d[mb][nb][2], d[mb][nb][3]);
            }
        }
    }

    if (STATS){
        float* sred = reinterpret_cast<float*>(smem + 2*SMBUF);
        sred[tid] = 0.f;
        __syncthreads();
        float s[16], q[16];
        #pragma unroll
        for (int i=0;i<16;i++){ s[i]=0.f; q[i]=0.f; }
        #pragma unroll
        for (int mb=0; mb<2; mb++)
            #pragma unroll
            for (int nb=0; nb<8; nb++){
                s[nb*2+0] += d[mb][nb][0] + d[mb][nb][2];
                s[nb*2+1] += d[mb][nb][1] + d[mb][nb][3];
                q[nb*2+0] += d[mb][nb][0]*d[mb][nb][0] + d[mb][nb][2]*d[mb][nb][2];
                q[nb*2+1] += d[mb][nb][1]*d[mb][nb][1] + d[mb][nb][3]*d[mb][nb][3];
            }
        #pragma unroll
        for (int off=4; off<32; off<<=1){
            #pragma unroll
            for (int i=0;i<16;i++){
                s[i] += __shfl_xor_sync(0xFFFFFFFFu, s[i], off);
                q[i] += __shfl_xor_sync(0xFFFFFFFFu, q[i], off);
            }
        }
        if (lane < 4){
            #pragma unroll
            for (int i=0;i<16;i++){
                const int col = warpn*64 + (i>>1)*8 + (lane & 3)*2 + (i & 1);
                atomicAdd(&sred[col], s[i]);
                atomicAdd(&sred[128+col], q[i]);
            }
        }
        __syncthreads();
        if (tid < 128){
            atomicAdd(&g_sum  [bcol + tid], sred[tid]);
            atomicAdd(&g_sumsq[bcol + tid], sred[128 + tid]);
        }
    }
}

// ================= spectral forward (256 blocks, red.add into fp32 HS) =================
#define SSMBUF 34816
__global__ void __launch_bounds__(256,2) spec5(float* __restrict__ HS)
{
    extern __shared__ __align__(16) uint8_t smem[];
    const uint32_t sb = smem_u32(smem);
    const int b   = blockIdx.z;
    const int seg = blockIdx.x;
    const __nv_bfloat16* Ahi = g_eihi + (size_t)b*V_*K_;
    const __nv_bfloat16* Alo = g_eilo + (size_t)b*V_*K_;
    const __nv_bfloat16* Bhi = g_hhi  + (size_t)b*V_*H_;
    const __nv_bfloat16* Blo = g_hlo  + (size_t)b*V_*H_;

    const int tid = threadIdx.x;
    const int lane = tid & 31, wid = tid >> 5;
    const int warpm = wid & 3, warpn = wid >> 2;
    const int vr = tid >> 3, cs = (tid & 7) * 16;
    const int v0 = seg * (V_/SPLITV);
    const int nch = V_/SPLITV/32;   // 16

    auto stage = [&](int vc, int buf){
        const int v = v0 + vc*32 + vr;
        const size_t soA = (size_t)v*K_ + cs;
        const size_t soB = (size_t)v*H_ + cs;
        const uint32_t base = sb + buf*SSMBUF + vr*BPITCH + cs*2;
        cpasync16(base,              Ahi + soA);
        cpasync16(base + 16,         Ahi + soA + 8);
        cpasync16(base + 8704,       Alo + soA);
        cpasync16(base + 8704 + 16,  Alo + soA + 8);
        cpasync16(base + 17408,      Bhi + soB);
        cpasync16(base + 17408 + 16, Bhi + soB + 8);
        cpasync16(base + 26112,      Blo + soB);
        cpasync16(base + 26112 + 16, Blo + soB + 8);
    };

    float d[2][8][4];
    #pragma unroll
    for (int i=0;i<2;i++)
        #pragma unroll
        for (int j=0;j<8;j++)
            #pragma unroll
            for (int q=0;q<4;q++) d[i][j][q] = 0.f;

    stage(0, 0);
    CP_COMMIT();
    CP_WAIT0();
    __syncthreads();

    for (int vc = 0; vc < nch; vc++){
        const int cur = vc & 1, nxt = cur ^ 1;
        const bool more = (vc + 1 < nch);
        if (more){ stage(vc+1, nxt); CP_COMMIT(); }

        const uint32_t aHi = sb + cur*SSMBUF;
        const uint32_t aLo = aHi + 8704;
        const uint32_t bHi = aHi + 17408;
        const uint32_t bLo = aHi + 26112;
        #pragma unroll
        for (int ks=0; ks<2; ks++){
            uint32_t ah[2][4], al[2][4];
            #pragma unroll
            for (int mb=0; mb<2; mb++){
                const uint32_t ao = (uint32_t)(ks*16 + (lane & 7) + ((lane >> 4)*8))*BPITCH
                                  + (uint32_t)(warpm*32 + mb*16)*2 + (((lane >> 3) & 1)*16);
                ldsm4t(ah[mb], aHi + ao);
                ldsm4t(al[mb], aLo + ao);
            }
            #pragma unroll
            for (int np=0; np<4; np++){
                const int n0 = warpn*64 + np*16;
                const uint32_t bo = (uint32_t)(ks*16 + (lane & 15))*BPITCH
                                  + (uint32_t)n0*2 + ((lane >> 4)*16);
                uint32_t bh[4], bl[4];
                ldsm4t(bh, bHi + bo);
                ldsm4t(bl, bLo + bo);
                #pragma unroll
                for (int mb=0; mb<2; mb++){
                    mma16816(d[mb][np*2  ], ah[mb], bh[0], bh[1]);
                    mma16816(d[mb][np*2  ], al[mb], bh[0], bh[1]);
                    mma16816(d[mb][np*2  ], ah[mb], bl[0], bl[1]);
                    mma16816(d[mb][np*2+1], ah[mb], bh[2], bh[3]);
                    mma16816(d[mb][np*2+1], al[mb], bh[2], bh[3]);
                    mma16816(d[mb][np*2+1], ah[mb], bl[2], bl[3]);
                }
            }
        }
        if (more) CP_WAIT0();
        __syncthreads();
    }

    float* Cb = HS + (size_t)b*K_*H_;
    #pragma unroll
    for (int mb=0; mb<2; mb++)
        #pragma unroll
        for (int nb=0; nb<8; nb++){
            const int m = warpm*32 + mb*16 + (lane >> 2);
            const int n = warpn*64 + nb*8 + (lane & 3)*2;
            red_add_v2(Cb + (size_t)m*H_ + n,     d[mb][nb][0], d[mb][nb][1]);
            red_add_v2(Cb + (size_t)(m+8)*H_ + n, d[mb][nb][2], d[mb][nb][3]);
        }
}

// HS -> coeff * HS, split to bf16 hi/lo
__global__ void coeff_mul_split(const float* __restrict__ eigs, const float* __restrict__ pt,
                                const float* __restrict__ HS, int l)
{
    const int b = blockIdx.y, k = blockIdx.x, h = threadIdx.x;
    const float ev = eigs[(size_t)b*(2*V_+1)*K_ + k];
    const float t  = fmaxf(pt[l*H_ + h], 1e-6f);
    const size_t i = ((size_t)b*K_ + k)*H_ + h;
    const float v = HS[i] * __expf(-ev*t);
    __nv_bfloat16 hi, lo; split1(v, hi, lo);
    g_hshi[i] = hi; g_hslo[i] = lo;
}

// finalize BN coeffs; zeroes stats for the next accumulation
__global__ void finalize_bn(const float* __restrict__ g, const float* __restrict__ be, float Rinv){
    const int c = threadIdx.x;
    const float m   = g_sum[c]*Rinv;
    const float var = g_sumsq[c]*Rinv - m*m;
    const float sc  = g[c] * rsqrtf(var + EPSF);
    g_scale[c] = sc;
    g_shift[c] = be[c] - m*sc;
    g_sum[c] = 0.f;
    g_sumsq[c] = 0.f;
}

// ---------------- message + scatter-add ----------------
__global__ void msg_scatter(const float* __restrict__ Y2, const int* __restrict__ vid,
                            float* __restrict__ Hout)
{
    const int sub = threadIdx.x >> 5;
    const int c4  = (threadIdx.x & 31) * 4;
    const int e0  = blockIdx.x * 32 + sub * 8;
    const float s0=g_scale[c4],   s1=g_scale[c4+1],   s2=g_scale[c4+2],   s3=g_scale[c4+3];
    const float t0=g_shift[c4],   t1=g_shift[c4+1],   t2=g_shift[c4+2],   t3=g_shift[c4+3];
    const float u0=g_scale[128+c4],u1=g_scale[129+c4],u2=g_scale[130+c4],u3=g_scale[131+c4];
    const float w0=g_shift[128+c4],w1=g_shift[129+c4],w2=g_shift[130+c4],w3=g_shift[131+c4];
    #pragma unroll
    for (int i=0;i<8;i++){
        const int e = e0 + i;
        float4 f = *reinterpret_cast<const float4*>(Y2 + (size_t)e*256 + c4);
        float4 c = *reinterpret_cast<const float4*>(Y2 + (size_t)e*256 + 128 + c4);
        float m0 = (1.f/(1.f+__expf(-(f.x*s0+t0)))) * softplusf(c.x*u0+w0);
        float m1 = (1.f/(1.f+__expf(-(f.y*s1+t1)))) * softplusf(c.y*u1+w1);
        float m2 = (1.f/(1.f+__expf(-(f.z*s2+t2)))) * softplusf(c.z*u2+w2);
        float m3 = (1.f/(1.f+__expf(-(f.w*s3+t3)))) * softplusf(c.w*u3+w3);
        const int v = vid[e];
        red_add_v4(Hout + (size_t)v*128 + c4, m0, m1, m2, m3);
    }
}

// h += bn(Y); also emit split H
__global__ void h_update_split(float* __restrict__ H, const float* __restrict__ Y){
    const size_t i = (size_t)blockIdx.x*256 + threadIdx.x;
    const int c = (int)(i & 127);
    const float v = H[i] + Y[i]*g_scale[c] + g_shift[c];
    H[i] = v;
    __nv_bfloat16 hi, lo; split1(v, hi, lo);
    g_hhi[i] = hi; g_hlo[i] = lo;
}
__global__ void split_H(const float* __restrict__ H){
    const size_t i = (size_t)blockIdx.x*256 + threadIdx.x;
    __nv_bfloat16 hi, lo; split1(H[i], hi, lo);
    g_hhi[i] = hi; g_hlo[i] = lo;
}

// out[b] += mean_v( silu(bn(Yo)) . wo2 + bo2 )
__global__ void out_reduce(const float* __restrict__ Yo, const float* __restrict__ wo2,
                           const float* __restrict__ bo2, float* __restrict__ out)
{
    const int warp = threadIdx.x >> 5, lane = threadIdx.x & 31;
    const long n = (long)blockIdx.x*8 + warp;
    float s = 0.f;
    #pragma unroll
    for (int j=0;j<4;j++){
        const int h = lane + j*32;
        float x = Yo[(size_t)n*128 + h]*g_scale[h] + g_shift[h];
        x = siluf(x);
        s += x * wo2[h];
    }
    #pragma unroll
    for (int o=16;o>0;o>>=1) s += __shfl_xor_sync(0xFFFFFFFFu, s, o);
    if (lane == 0){
        const int b = (int)(n >> 11);
        atomicAdd(&out[b], (s + bo2[0]) * (1.f/(float)V_));
    }
}

// ---------------- launcher ----------------
extern "C" void kernel_launch(void* const* d_in, const int* in_sizes, int n_in,
                              void* d_out, int out_size)
{
    const float* chem = (const float*)d_in[0];
    const int*   vid  = (const int*  )d_in[1];
    const float* eigs = (const float*)d_in[2];
    const float* w1   = (const float*)d_in[3];
    const float* b1   = (const float*)d_in[4];
    const float* g1   = (const float*)d_in[5];
    const float* be1  = (const float*)d_in[6];
    const float* w2   = (const float*)d_in[7];
    const float* b2   = (const float*)d_in[8];
    const float* g2   = (const float*)d_in[9];
    const float* be2  = (const float*)d_in[10];
    const float* ptim = (const float*)d_in[11];
    const float* pw1  = (const float*)d_in[12];
    const float* pb1  = (const float*)d_in[13];
    const float* pg1  = (const float*)d_in[14];
    const float* pbe1 = (const float*)d_in[15];
    const float* pw2  = (const float*)d_in[16];
    const float* pb2  = (const float*)d_in[17];
    const float* pg2  = (const float*)d_in[18];
    const float* pbe2 = (const float*)d_in[19];
    const float* wo1  = (const float*)d_in[20];
    const float* bo1  = (const float*)d_in[21];
    const float* go1  = (const float*)d_in[22];
    const float* beo1 = (const float*)d_in[23];
    const float* wo2  = (const float*)d_in[24];
    const float* bo2  = (const float*)d_in[25];
    float* outp = (float*)d_out;

    void* p;
    float *pY1,*pY2,*pH,*pHS,*pYa,*pYb;
    __nv_bfloat16 *pw1hi,*pw1lo,*pw2hi,*pw2lo,*ppw1hi,*ppw1lo,*ppw2hi,*ppw2lo,*pwo1hi,*pwo1lo;
    __nv_bfloat16 *pevhi,*pevlo,*phshi,*phslo,*phhi,*phlo,*pThi,*pTlo;
    cudaGetSymbolAddress(&p, g_Y1); pY1=(float*)p;
    cudaGetSymbolAddress(&p, g_Y2); pY2=(float*)p;
    cudaGetSymbolAddress(&p, g_H ); pH =(float*)p;
    cudaGetSymbolAddress(&p, g_HS); pHS=(float*)p;
    cudaGetSymbolAddress(&p, g_Ya); pYa=(float*)p;
    cudaGetSymbolAddress(&p, g_Yb); pYb=(float*)p;
    cudaGetSymbolAddress(&p, w1s_hi); pw1hi=(__nv_bfloat16*)p;
    cudaGetSymbolAddress(&p, w1s_lo); pw1lo=(__nv_bfloat16*)p;
    cudaGetSymbolAddress(&p, w2s_hi); pw2hi=(__nv_bfloat16*)p;
    cudaGetSymbolAddress(&p, w2s_lo); pw2lo=(__nv_bfloat16*)p;
    cudaGetSymbolAddress(&p, pw1s_hi); ppw1hi=(__nv_bfloat16*)p;
    cudaGetSymbolAddress(&p, pw1s_lo); ppw1lo=(__nv_bfloat16*)p;
    cudaGetSymbolAddress(&p, pw2s_hi); ppw2hi=(__nv_bfloat16*)p;
    cudaGetSymbolAddress(&p, pw2s_lo); ppw2lo=(__nv_bfloat16*)p;
    cudaGetSymbolAddress(&p, wo1s_hi); pwo1hi=(__nv_bfloat16*)p;
    cudaGetSymbolAddress(&p, wo1s_lo); pwo1lo=(__nv_bfloat16*)p;
    cudaGetSymbolAddress(&p, g_evhi); pevhi=(__nv_bfloat16*)p;
    cudaGetSymbolAddress(&p, g_evlo); pevlo=(__nv_bfloat16*)p;
    cudaGetSymbolAddress(&p, g_hshi); phshi=(__nv_bfloat16*)p;
    cudaGetSymbolAddress(&p, g_hslo); phslo=(__nv_bfloat16*)p;
    cudaGetSymbolAddress(&p, g_hhi ); phhi=(__nv_bfloat16*)p;
    cudaGetSymbolAddress(&p, g_hlo ); phlo=(__nv_bfloat16*)p;
    cudaGetSymbolAddress(&p, g_Thi ); pThi=(__nv_bfloat16*)p;
    cudaGetSymbolAddress(&p, g_Tlo ); pTlo=(__nv_bfloat16*)p;

    const int GSM = 2*SMBUF + 1024;
    const int SSM = 2*SSMBUF;
    cudaFuncSetAttribute(gemm5<0,true ,false>, cudaFuncAttributeMaxDynamicSharedMemorySize, GSM);
    cudaFuncSetAttribute(gemm5<1,true ,false>, cudaFuncAttributeMaxDynamicSharedMemorySize, GSM);
    cudaFuncSetAttribute(gemm5<3,false,true >, cudaFuncAttributeMaxDynamicSharedMemorySize, GSM);
    cudaFuncSetAttribute(gemm5<5,true ,false>, cudaFuncAttributeMaxDynamicSharedMemorySize, GSM);
    cudaFuncSetAttribute(gemm5<3,true ,false>, cudaFuncAttributeMaxDynamicSharedMemorySize, GSM);
    cudaFuncSetAttribute(spec5, cudaFuncAttributeMaxDynamicSharedMemorySize, SSM);

    zero_kernel<<<1, 64>>>(outp, 64);
    zero_stats<<<1,256>>>();

    // ---- prep ----
    split_w1<<<64*128/256, 256>>>(w1);
    split_mat<<<(128*256+255)/256, 256>>>(w2, pw2hi, pw2lo, 128*256);
    split_mat<<<(3*256*128+255)/256, 256>>>(pw1, ppw1hi, ppw1lo, 3*256*128);
    split_mat<<<(3*128*128+255)/256, 256>>>(pw2, ppw2hi, ppw2lo, 3*128*128);
    split_mat<<<(128*128+255)/256, 256>>>(wo1, pwo1hi, pwo1lo, 128*128);
    split_eigs_k<<<(unsigned)(((size_t)B_*V_*K_)/256), 256>>>(eigs);

    // ---- chem MLP stage 1 ----
    gemm5<0,true,false><<<dim3(1, E_/128, 1), 256, GSM>>>(
        chem, nullptr, nullptr, nullptr, nullptr, pw1hi, pw1lo, nullptr, nullptr,
        b1, pY1, nullptr, nullptr, CF_, 128, CF_, 0, 0, 0);
    finalize_bn<<<1,128>>>(g1, be1, 1.f/(float)E_);

    // ---- stage 2 ----
    gemm5<1,true,false><<<dim3(2, E_/128, 1), 256, GSM>>>(
        pY1, nullptr, nullptr, nullptr, nullptr, pw2hi, pw2lo, nullptr, nullptr,
        b2, pY2, nullptr, nullptr, 128, 256, 128, 0, 0, 0);
    finalize_bn<<<1,256>>>(g2, be2, 1.f/(float)E_);

    // ---- message + segment_sum ----
    zero_kernel<<<(unsigned)(((size_t)N_*H_)/256), 256>>>(pH, (size_t)N_*H_);
    msg_scatter<<<E_/32, 128>>>(pY2, vid, pH);
    split_H<<<(unsigned)(((size_t)N_*H_)/256), 256>>>(pH);

    // ---- propagation layers ----
    for (int l = 0; l < L_; l++){
        // HS = evinv^T @ h  (256 blocks, red.add)
        zero_kernel<<<(B_*K_*H_+255)/256, 256>>>(pHS, (size_t)B_*K_*H_);
        spec5<<<dim3(SPLITV, 1, B_), 256, SSM>>>(pHS);
        // HS' = coeff .* HS, split
        coeff_mul_split<<<dim3(K_,B_), H_>>>(eigs, ptim, pHS, l);
        // T[b] = HS'[b] @ W1b
        gemm5<3,false,true><<<dim3(1, 1, B_), 256, GSM>>>(
            nullptr, phshi, phslo, nullptr, nullptr,
            ppw1hi + (size_t)l*256*128 + 128*128, ppw1lo + (size_t)l*256*128 + 128*128,
            nullptr, nullptr, nullptr, nullptr, pThi, pTlo,
            128, 128, 128, (size_t)K_*H_, 0, (size_t)K_*H_);
        // zMLP1: Ya = h @ W1a + evecs @ T[b] + pb1[l]
        gemm5<5,true,false><<<dim3(1, N_/128, 1), 256, GSM>>>(
            nullptr, phhi, phlo, pevhi, pevlo,
            ppw1hi + (size_t)l*256*128, ppw1lo + (size_t)l*256*128, pThi, pTlo,
            pb1 + l*H_, pYa, nullptr, nullptr, 256, 128, 128, 0, 0, 0);
        finalize_bn<<<1,128>>>(pg1 + l*H_, pbe1 + l*H_, 1.f/(float)N_);
        // zMLP2: Yb = silu(bn(Ya)) @ pw2[l] + pb2[l]
        gemm5<1,true,false><<<dim3(1, N_/128, 1), 256, GSM>>>(
            pYa, nullptr, nullptr, nullptr, nullptr,
            ppw2hi + (size_t)l*128*128, ppw2lo + (size_t)l*128*128, nullptr, nullptr,
            pb2 + l*H_, pYb, nullptr, nullptr, 128, 128, 128, 0, 0, 0);
        finalize_bn<<<1,128>>>(pg2 + l*H_, pbe2 + l*H_, 1.f/(float)N_);
        h_update_split<<<(unsigned)(((size_t)N_*H_)/256), 256>>>(pH, pYb);
    }

    // ---- output head ----
    gemm5<3,true,false><<<dim3(1, N_/128, 1), 256, GSM>>>(
        nullptr, phhi, phlo, nullptr, nullptr, pwo1hi, pwo1lo, nullptr, nullptr,
        bo1, pYa, nullptr, nullptr, 128, 128, 128, 0, 0, 0);
    finalize_bn<<<1,128>>>(go1, beo1, 1.f/(float)N_);
    out_reduce<<<N_/8, 256>>>(pYa, wo2, bo2, outp);
}